// round 7
// baseline (speedup 1.0000x reference)
#include <cuda_runtime.h>
#include <cuda_fp16.h>
#include <mma.h>
#include <math.h>
#include <stdint.h>

using namespace nvcuda;

#define N_TOK 32768
#define NB 64
#define NP 512
#define D 128
#define M 256
#define DV 256
#define EPS_PHI 1e-4f
#define EPS_NORM 1e-8f
#define INV_SQRT_M 0.0625f
#define XSCALE 0.29730177875068026f   // 1/128^0.25
#define KSCALE 256.0f
#define QSCALE 256.0f
#define ESCALE 512.0f
#define C2F (EPS_PHI * INV_SQRT_M * KSCALE)          // Kp eps term (scaled)
#define NORM_EPS (EPS_NORM * KSCALE * QSCALE)

// ---------------- scratch ------------------------------------------------------
__device__ float  g_segmax[NB];
__device__ float  g_bmax[N_TOK / 128];
__device__ float  g_esum[(N_TOK / 128) * M];
__device__ __align__(16) __half g_Qh[N_TOK * M];   // scaled phi(Q) [t][m]
__device__ __align__(16) __half g_Ke[N_TOK * M];   // exp(U-h-bmax)*ESCALE [t][m]
__device__ __align__(16) __half g_Whi[D * M];
__device__ __align__(16) __half g_Wlo[D * M];

__device__ __forceinline__ void atomicMaxF(float* addr, float val) {
    int* ia = (int*)addr;
    int old = *ia;
    while (__int_as_float(old) < val) {
        int assumed = old;
        old = atomicCAS(ia, assumed, __float_as_int(val));
        if (old == assumed) break;
    }
}

__device__ __forceinline__ void cp16(uint32_t dst, const void* src) {
    asm volatile("cp.async.cg.shared.global [%0], [%1], 16;" :: "r"(dst), "l"(src));
}

__global__ void omega_split_kernel(const float* __restrict__ omega) {
    int i = blockIdx.x * 256 + threadIdx.x;
    float w = omega[i];
    __half hi = __float2half_rn(w);
    g_Whi[i] = hi;
    g_Wlo[i] = __float2half_rn(w - __half2float(hi));
    if (blockIdx.x == 0 && threadIdx.x < NB) g_segmax[threadIdx.x] = -INFINITY;
}

// ---------------- phi via split-fp16 wmma (unchanged from R6) ----------------
#define PHI_LDA 136
#define PHI_LDB 264
#define PHI_LDC 260
#define PHI_SMEM 209920

__global__ __launch_bounds__(512, 1) void phi_wmma_kernel(
    const float* __restrict__ Q, const float* __restrict__ K) {
    extern __shared__ char smraw[];
    __half* Ahi = (__half*)smraw;
    __half* Alo = (__half*)(smraw + 34816);
    __half* Bhi = (__half*)(smraw + 69632);
    __half* Blo = (__half*)(smraw + 137216);
    float*  Cs  = (float*)smraw;
    float*  hsm = (float*)(smraw + 204800);
    float*  mxs = (float*)(smraw + 205312);
    float2* esb = (float2*)(smraw + 205824);

    const int tid  = threadIdx.x;
    const int warp = tid >> 5, lane = tid & 31;
    const bool isq = blockIdx.x < (N_TOK / 128);
    const int tile = isq ? blockIdx.x : blockIdx.x - (N_TOK / 128);
    const int row0 = tile * 128;
    const float* X = isq ? Q : K;

    {
        int r = tid >> 2, j = tid & 3;
        const float4* src = (const float4*)(X + (size_t)(row0 + r) * D + j * 32);
        __half* ah = Ahi + r * PHI_LDA + j * 32;
        __half* al = Alo + r * PHI_LDA + j * 32;
        float ss = 0.f;
#pragma unroll
        for (int q = 0; q < 8; q++) {
            float4 v = src[q];
            v.x *= XSCALE; v.y *= XSCALE; v.z *= XSCALE; v.w *= XSCALE;
            ss += v.x * v.x + v.y * v.y + v.z * v.z + v.w * v.w;
            __half hx = __float2half_rn(v.x), hy = __float2half_rn(v.y);
            __half hz = __float2half_rn(v.z), hw = __float2half_rn(v.w);
            ((__half2*)(ah + q * 4))[0] = __halves2half2(hx, hy);
            ((__half2*)(ah + q * 4))[1] = __halves2half2(hz, hw);
            ((__half2*)(al + q * 4))[0] = __floats2half2_rn(v.x - __half2float(hx),
                                                            v.y - __half2float(hy));
            ((__half2*)(al + q * 4))[1] = __floats2half2_rn(v.z - __half2float(hz),
                                                            v.w - __half2float(hw));
        }
        ss += __shfl_xor_sync(0xffffffffu, ss, 1);
        ss += __shfl_xor_sync(0xffffffffu, ss, 2);
        if (j == 0) hsm[r] = 0.5f * ss;
    }
#pragma unroll
    for (int it = 0; it < 16; it++) {
        int i = it * 512 + tid;
        int sel = i >> 12;
        int j = i & 4095;
        int rr = j >> 5, c8 = j & 31;
        uint4 v = sel ? ((const uint4*)g_Wlo)[j] : ((const uint4*)g_Whi)[j];
        *(uint4*)((sel ? Blo : Bhi) + rr * PHI_LDB + c8 * 8) = v;
    }
    __syncthreads();

    const int wr = warp >> 2, wc = warp & 3;
    wmma::fragment<wmma::accumulator, 16, 16, 16, float> c[2][4];
#pragma unroll
    for (int i = 0; i < 2; i++)
#pragma unroll
        for (int j = 0; j < 4; j++) wmma::fill_fragment(c[i][j], 0.f);

#pragma unroll
    for (int ks = 0; ks < 8; ks++) {
        int kk = ks * 16;
        wmma::fragment<wmma::matrix_a, 16, 16, 16, __half, wmma::row_major> ah[2], al[2];
        wmma::fragment<wmma::matrix_b, 16, 16, 16, __half, wmma::row_major> bh[4], bl[4];
#pragma unroll
        for (int i = 0; i < 2; i++) {
            wmma::load_matrix_sync(ah[i], Ahi + (wr * 32 + i * 16) * PHI_LDA + kk, PHI_LDA);
            wmma::load_matrix_sync(al[i], Alo + (wr * 32 + i * 16) * PHI_LDA + kk, PHI_LDA);
        }
#pragma unroll
        for (int j = 0; j < 4; j++) {
            wmma::load_matrix_sync(bh[j], Bhi + kk * PHI_LDB + wc * 64 + j * 16, PHI_LDB);
            wmma::load_matrix_sync(bl[j], Blo + kk * PHI_LDB + wc * 64 + j * 16, PHI_LDB);
        }
#pragma unroll
        for (int i = 0; i < 2; i++)
#pragma unroll
            for (int j = 0; j < 4; j++) {
                wmma::mma_sync(c[i][j], ah[i], bh[j], c[i][j]);
                wmma::mma_sync(c[i][j], al[i], bh[j], c[i][j]);
                wmma::mma_sync(c[i][j], ah[i], bl[j], c[i][j]);
            }
    }
    __syncthreads();

    if (isq) {
#pragma unroll
        for (int i = 0; i < 2; i++)
#pragma unroll
            for (int j = 0; j < 4; j++)
                wmma::store_matrix_sync(Cs + (wr * 32 + i * 16) * PHI_LDC + wc * 64 + j * 16,
                                        c[i][j], PHI_LDC, wmma::mem_row_major);
        __syncthreads();
#pragma unroll
        for (int rr = 0; rr < 8; rr++) {
            int row = warp * 8 + rr;
            float mx = -INFINITY;
#pragma unroll
            for (int cc = lane; cc < M; cc += 32) mx = fmaxf(mx, Cs[row * PHI_LDC + cc]);
#pragma unroll
            for (int o = 16; o > 0; o >>= 1) mx = fmaxf(mx, __shfl_xor_sync(0xffffffffu, mx, o));
            if (lane == 0) mxs[row] = mx;
        }
        __syncthreads();
#pragma unroll
        for (int it = 0; it < 32; it++) {
            int i = it * 512 + tid;
            int row = i >> 7, c2 = i & 127;
            float hm = hsm[row] + mxs[row];
            float2 u = *(const float2*)&Cs[row * PHI_LDC + c2 * 2];
            float a = (__expf(u.x - hm) + EPS_PHI) * (INV_SQRT_M * QSCALE);
            float b = (__expf(u.y - hm) + EPS_PHI) * (INV_SQRT_M * QSCALE);
            ((__half2*)g_Qh)[(size_t)(row0 + row) * (M / 2) + c2] = __floats2half2_rn(a, b);
        }
    } else {
        float bm = -INFINITY;
#pragma unroll
        for (int i = 0; i < 2; i++)
#pragma unroll
            for (int j = 0; j < 4; j++)
#pragma unroll
                for (int e = 0; e < c[i][j].num_elements; e++)
                    bm = fmaxf(bm, c[i][j].x[e]);
#pragma unroll
        for (int o = 16; o > 0; o >>= 1) bm = fmaxf(bm, __shfl_xor_sync(0xffffffffu, bm, o));
        if (lane == 0) mxs[warp] = bm;
        __syncthreads();
#pragma unroll
        for (int i = 0; i < 2; i++)
#pragma unroll
            for (int j = 0; j < 4; j++)
                wmma::store_matrix_sync(Cs + (wr * 32 + i * 16) * PHI_LDC + wc * 64 + j * 16,
                                        c[i][j], PHI_LDC, wmma::mem_row_major);
        float bmax = mxs[0];
#pragma unroll
        for (int w = 1; w < 16; w++) bmax = fmaxf(bmax, mxs[w]);
        __syncthreads();
        float2 es = make_float2(0.f, 0.f);
#pragma unroll
        for (int it = 0; it < 32; it++) {
            int i = it * 512 + tid;
            int row = i >> 7, c2 = i & 127;
            float hm = hsm[row] + bmax;
            float2 u = *(const float2*)&Cs[row * PHI_LDC + c2 * 2];
            float a = __expf(u.x - hm) * ESCALE;
            float b = __expf(u.y - hm) * ESCALE;
            es.x += a; es.y += b;
            ((__half2*)g_Ke)[(size_t)(row0 + row) * (M / 2) + c2] = __floats2half2_rn(a, b);
        }
        esb[tid] = es;
        __syncthreads();
        if (tid < 128) {
            float2 t0 = esb[tid], t1 = esb[tid + 128];
            float2 t2 = esb[tid + 256], t3 = esb[tid + 384];
            g_esum[tile * M + tid * 2]     = t0.x + t1.x + t2.x + t3.x;
            g_esum[tile * M + tid * 2 + 1] = t0.y + t1.y + t2.y + t3.y;
        }
        if (tid == 0) {
            g_bmax[tile] = bmax;
            atomicMaxF(&g_segmax[tile >> 2], bmax);
        }
    }
}

// ---------------- fused segment kernel ---------------------------------------
// grid (2, 64): vh half, segment b. 512 threads.
// Phase 1: KVs[m 0..255][v-half 0..127] = sum_t Ke[t][m] * (corr*V[t][v]) in smem
// Phase 2: out[t][v] = (Qp_chunk @ KVs + qsum*C2F*Vsum) / norm
#define LDA 264          // [t][m] tiles, 256 + 8 pad
#define LDB 136          // v tiles, 128 + 8 pad
#define LDC 132
#define KVS_OFF 0        // half [256][136]              = 69632
#define ST_OFF  69632    // 2 stages x (A 33792 + B 17408) = 102400
#define ST_SZ   51200
#define AS2_OFF 69632    // phase-2 A chunk half [128][264] = 67584
#define CS_OFF  139264   // float [128][132] = 67584
#define KSM_OFF 206848   // float [256]
#define NORM_OFF 207872  // float [128]
#define QSUM_OFF 208384  // float [128]
#define VSUM_OFF 208896  // float [128]
#define SMEMF   209408

__global__ __launch_bounds__(512, 1) void fused_kernel(const float* __restrict__ V,
                                                       float* __restrict__ out) {
    extern __shared__ char smraw[];
    __half* KVs  = (__half*)smraw;
    float*  ksm  = (float*)(smraw + KSM_OFF);
    float*  normbuf = (float*)(smraw + NORM_OFF);
    float*  qsumbuf = (float*)(smraw + QSUM_OFF);
    float*  vsum = (float*)(smraw + VSUM_OFF);
    const uint32_t sbase = (uint32_t)__cvta_generic_to_shared(smraw);

    const int tid = threadIdx.x, warp = tid >> 5;
    const int vh = blockIdx.x, b = blockIdx.y;

    // --- Ksum in smem (from phi partials) + vsum init ---
    const float sgm = g_segmax[b];
    if (tid < M) {
        float s = 0.f;
#pragma unroll
        for (int cb = 0; cb < 4; cb++)
            s += __expf(g_bmax[b * 4 + cb] - sgm) * g_esum[(b * 4 + cb) * M + tid];
        ksm[tid] = (s * (1.f / ESCALE) + NP * EPS_PHI) * (INV_SQRT_M * KSCALE);
    }
    if (tid < 128) vsum[tid] = 0.f;

    float corrf[4];
#pragma unroll
    for (int cb = 0; cb < 4; cb++)
        corrf[cb] = __expf(g_bmax[b * 4 + cb] - sgm) * (INV_SQRT_M * KSCALE / ESCALE);

    const __half* Ke = g_Ke + (size_t)b * NP * M;
    const float*  Vb = V    + (size_t)b * NP * DV + vh * 128;

    // ================= PHASE 1: KV-half into smem =================
    // warp tile: 32 m x 64 v; wr=warp&7 (m), wv=warp>>3 (v)
    const int wr = warp & 7, wv = warp >> 3;

    auto copyA = [&](int s, int ch) {   // Ke rows ch*64..+64, all 256 m
        uint32_t abase = sbase + ST_OFF + s * ST_SZ;
        const __half* src = Ke + (size_t)(ch * 64) * M;
#pragma unroll
        for (int u = 0; u < 4; u++) {
            int i = tid + u * 512, t = i >> 5, q = i & 31;
            cp16(abase + (t * LDA + q * 8) * 2, src + (size_t)t * M + q * 8);
        }
        asm volatile("cp.async.commit_group;");
    };

    float4 Breg[4], Breg2[4];
    auto loadB = [&](float4* rg, int ch) {
        const float* src = Vb + (size_t)(ch * 64) * DV;
#pragma unroll
        for (int u = 0; u < 4; u++) {
            int i = tid + u * 512, t = i >> 5, q = i & 31;
            rg[u] = ((const float4*)(src + (size_t)t * DV))[q];
        }
    };
    float4 vpart = make_float4(0.f, 0.f, 0.f, 0.f);
    auto storeB = [&](const float4* rg, int s, float cf) {
        __half* Bs = (__half*)(smraw + ST_OFF + s * ST_SZ + 33792);
#pragma unroll
        for (int u = 0; u < 4; u++) {
            int i = tid + u * 512, t = i >> 5, q = i & 31;
            float4 f = rg[u];
            vpart.x += f.x; vpart.y += f.y; vpart.z += f.z; vpart.w += f.w;
            ((__half2*)(Bs + t * LDB))[q * 2]     = __floats2half2_rn(f.x * cf, f.y * cf);
            ((__half2*)(Bs + t * LDB))[q * 2 + 1] = __floats2half2_rn(f.z * cf, f.w * cf);
        }
    };

    wmma::fragment<wmma::accumulator, 16, 16, 16, float> c1[2][4];
#pragma unroll
    for (int i = 0; i < 2; i++)
#pragma unroll
        for (int j = 0; j < 4; j++) wmma::fill_fragment(c1[i][j], 0.f);

    copyA(0, 0);
    loadB(Breg, 0);

    for (int ch = 0; ch < 8; ch++) {
        int s = ch & 1;
        if (ch < 7) copyA(s ^ 1, ch + 1);
        if (ch < 7) asm volatile("cp.async.wait_group 1;");
        else        asm volatile("cp.async.wait_group 0;");
        storeB(Breg, s, corrf[ch >> 1]);
        __syncthreads();
        if (ch < 7) loadB(Breg2, ch + 1);

        const __half* As = (const __half*)(smraw + ST_OFF + s * ST_SZ);
        const __half* Bs = As + 33792 / 2;
#pragma unroll
        for (int kk = 0; kk < 64; kk += 16) {
            wmma::fragment<wmma::matrix_a, 16, 16, 16, __half, wmma::col_major> a[2];
#pragma unroll
            for (int i = 0; i < 2; i++)
                wmma::load_matrix_sync(a[i], As + kk * LDA + wr * 32 + i * 16, LDA);
#pragma unroll
            for (int j = 0; j < 4; j++) {
                wmma::fragment<wmma::matrix_b, 16, 16, 16, __half, wmma::row_major> bf;
                wmma::load_matrix_sync(bf, Bs + kk * LDB + wv * 64 + j * 16, LDB);
#pragma unroll
                for (int i = 0; i < 2; i++)
                    wmma::mma_sync(c1[i][j], a[i], bf, c1[i][j]);
            }
        }
        __syncthreads();
#pragma unroll
        for (int u = 0; u < 4; u++) Breg[u] = Breg2[u];
    }

    // vsum: thread owns cols q*4..q*4+3
    {
        int q = tid & 31;
        atomicAdd(&vsum[q * 4 + 0], vpart.x);
        atomicAdd(&vsum[q * 4 + 1], vpart.y);
        atomicAdd(&vsum[q * 4 + 2], vpart.z);
        atomicAdd(&vsum[q * 4 + 3], vpart.w);
    }
    // KV -> smem fp16 (element-wise accumulator convert)
#pragma unroll
    for (int i = 0; i < 2; i++)
#pragma unroll
        for (int j = 0; j < 4; j++) {
            wmma::fragment<wmma::accumulator, 16, 16, 16, __half> hf;
#pragma unroll
            for (int e = 0; e < hf.num_elements; e++)
                hf.x[e] = __float2half_rn(c1[i][j].x[e]);
            wmma::store_matrix_sync(KVs + (wr * 32 + i * 16) * LDB + wv * 64 + j * 16,
                                    hf, LDB, wmma::mem_row_major);
        }

    // ================= PHASE 2: out chunks ========================
    // warp tile 32 t x 32 v; wr2=warp&3 (t), wc2=warp>>2 (v)
    const int wr2 = warp & 3, wc2 = warp >> 2;
    __half* As2 = (__half*)(smraw + AS2_OFF);
    float*  Cs  = (float*)(smraw + CS_OFF);
    const __half* Qh = g_Qh + (size_t)b * NP * M;

    for (int t0 = 0; t0 < 4; t0++) {
        // A chunk: 128 tokens x 256 m
        {
            uint32_t abase = sbase + AS2_OFF;
            const __half* src = Qh + (size_t)(t0 * 128) * M;
#pragma unroll
            for (int u = 0; u < 8; u++) {
                int i = tid + u * 512, r = i >> 5, q = i & 31;
                cp16(abase + (r * LDA + q * 8) * 2, src + (size_t)r * M + q * 8);
            }
            asm volatile("cp.async.commit_group;");
            asm volatile("cp.async.wait_group 0;");
        }
        __syncthreads();   // A ready; also covers KVs stores on t0==0

        // fused norm + qsum: 4 threads per row, 64 m each
        {
            int row = tid >> 2, q4 = tid & 3;
            const __half2* qrow = (const __half2*)(As2 + row * LDA + q4 * 64);
            const float* kk2 = ksm + q4 * 64;
            float np = 0.f, qs = 0.f;
#pragma unroll
            for (int mm = 0; mm < 32; mm++) {
                float2 q2 = __half22float2(qrow[mm]);
                np += q2.x * kk2[mm * 2] + q2.y * kk2[mm * 2 + 1];
                qs += q2.x + q2.y;
            }
            np += __shfl_xor_sync(0xffffffffu, np, 1);
            np += __shfl_xor_sync(0xffffffffu, np, 2);
            qs += __shfl_xor_sync(0xffffffffu, qs, 1);
            qs += __shfl_xor_sync(0xffffffffu, qs, 2);
            if (q4 == 0) { normbuf[row] = np; qsumbuf[row] = qs; }
        }

        wmma::fragment<wmma::accumulator, 16, 16, 16, float> c2[2][2];
#pragma unroll
        for (int i = 0; i < 2; i++)
#pragma unroll
            for (int j = 0; j < 2; j++) wmma::fill_fragment(c2[i][j], 0.f);

#pragma unroll
        for (int kk = 0; kk < 256; kk += 16) {
            wmma::fragment<wmma::matrix_a, 16, 16, 16, __half, wmma::row_major> a[2];
            wmma::fragment<wmma::matrix_b, 16, 16, 16, __half, wmma::row_major> bf[2];
#pragma unroll
            for (int i = 0; i < 2; i++)
                wmma::load_matrix_sync(a[i], As2 + (wr2 * 32 + i * 16) * LDA + kk, LDA);
#pragma unroll
            for (int j = 0; j < 2; j++)
                wmma::load_matrix_sync(bf[j], KVs + kk * LDB + wc2 * 32 + j * 16, LDB);
#pragma unroll
            for (int i = 0; i < 2; i++)
#pragma unroll
                for (int j = 0; j < 2; j++)
                    wmma::mma_sync(c2[i][j], a[i], bf[j], c2[i][j]);
        }
#pragma unroll
        for (int i = 0; i < 2; i++)
#pragma unroll
            for (int j = 0; j < 2; j++)
                wmma::store_matrix_sync(Cs + (wr2 * 32 + i * 16) * LDC + wc2 * 32 + j * 16,
                                        c2[i][j], LDC, wmma::mem_row_major);
        __syncthreads();

        float* op = out + ((size_t)(b * NP + t0 * 128)) * DV + vh * 128;
#pragma unroll
        for (int it = 0; it < 16; it++) {
            int i = it * 512 + tid;
            int e = i * 2, r = e >> 7, cc = e & 127;
            float inv = 1.0f / (normbuf[r] + NORM_EPS);
            float q1 = qsumbuf[r] * C2F;
            float2 v;
            v.x = (Cs[r * LDC + cc]     + q1 * vsum[cc])     * inv;
            v.y = (Cs[r * LDC + cc + 1] + q1 * vsum[cc + 1]) * inv;
            *(float2*)(op + (size_t)r * DV + cc) = v;
        }
        __syncthreads();
    }
}

// ---------------- launch ------------------------------------------------------
extern "C" void kernel_launch(void* const* d_in, const int* in_sizes, int n_in,
                              void* d_out, int out_size) {
    const float* Q     = (const float*)d_in[0];
    const float* K     = (const float*)d_in[1];
    const float* V     = (const float*)d_in[2];
    const float* omega = (const float*)d_in[3];
    float* out = (float*)d_out;

    cudaFuncSetAttribute(phi_wmma_kernel, cudaFuncAttributeMaxDynamicSharedMemorySize, PHI_SMEM);
    cudaFuncSetAttribute(fused_kernel,    cudaFuncAttributeMaxDynamicSharedMemorySize, SMEMF);

    omega_split_kernel<<<(D * M) / 256, 256>>>(omega);
    phi_wmma_kernel<<<2 * (N_TOK / 128), 512, PHI_SMEM>>>(Q, K);
    fused_kernel<<<dim3(2, NB), 512, SMEMF>>>(V, out);
}

// round 8
// speedup vs baseline: 1.0724x; 1.0724x over previous
#include <cuda_runtime.h>
#include <cuda_fp16.h>
#include <mma.h>
#include <math.h>
#include <stdint.h>

using namespace nvcuda;

#define N_TOK 32768
#define NB 64
#define NP 512
#define D 128
#define M 256
#define DV 256
#define EPS_PHI 1e-4f
#define EPS_NORM 1e-8f
#define INV_SQRT_M 0.0625f
#define XSCALE 0.29730177875068026f   // 1/128^0.25
#define KSCALE 256.0f
#define QSCALE 256.0f
#define ESCALE 512.0f
#define C2F (EPS_PHI * INV_SQRT_M * KSCALE)
#define NORM_EPS (EPS_NORM * KSCALE * QSCALE)

// ---------------- scratch ------------------------------------------------------
__device__ float  g_segmax[NB];
__device__ float  g_bmax[N_TOK / 128];
__device__ float  g_esum[(N_TOK / 128) * M];
__device__ __align__(16) __half g_Qh[N_TOK * M];
__device__ __align__(16) __half g_Ke[N_TOK * M];
__device__ __align__(16) __half g_Whi[D * M];

__device__ __forceinline__ void atomicMaxF(float* addr, float val) {
    int* ia = (int*)addr;
    int old = *ia;
    while (__int_as_float(old) < val) {
        int assumed = old;
        old = atomicCAS(ia, assumed, __float_as_int(val));
        if (old == assumed) break;
    }
}

__device__ __forceinline__ void cp16(uint32_t dst, const void* src) {
    asm volatile("cp.async.cg.shared.global [%0], [%1], 16;" :: "r"(dst), "l"(src));
}

__global__ void omega_split_kernel(const float* __restrict__ omega) {
    int i = blockIdx.x * 256 + threadIdx.x;
    g_Whi[i] = __float2half_rn(omega[i]);
    if (blockIdx.x == 0 && threadIdx.x < NB) g_segmax[threadIdx.x] = -INFINITY;
}

// ---------------- phi: U = Xhi@Whi + Xlo@Whi (split only on X) ----------------
#define PHI_LDA 136
#define PHI_LDB 264
#define PHI_LDC 260
#define PHI_SMEM 142336

__global__ __launch_bounds__(512, 1) void phi_wmma_kernel(
    const float* __restrict__ Q, const float* __restrict__ K) {
    extern __shared__ char smraw[];
    __half* Ahi = (__half*)smraw;
    __half* Alo = (__half*)(smraw + 34816);
    __half* Bhi = (__half*)(smraw + 69632);
    float*  Cs  = (float*)smraw;                 // [128][260] overlay
    float*  hsm = (float*)(smraw + 137216);
    float*  mxs = (float*)(smraw + 137728);
    float2* esb = (float2*)(smraw + 138240);     // [512]

    const int tid  = threadIdx.x;
    const int warp = tid >> 5, lane = tid & 31;
    const bool isq = blockIdx.x < (N_TOK / 128);
    const int tile = isq ? blockIdx.x : blockIdx.x - (N_TOK / 128);
    const int row0 = tile * 128;
    const float* X = isq ? Q : K;

    {
        int r = tid >> 2, j = tid & 3;
        const float4* src = (const float4*)(X + (size_t)(row0 + r) * D + j * 32);
        __half* ah = Ahi + r * PHI_LDA + j * 32;
        __half* al = Alo + r * PHI_LDA + j * 32;
        float ss = 0.f;
#pragma unroll
        for (int q = 0; q < 8; q++) {
            float4 v = src[q];
            v.x *= XSCALE; v.y *= XSCALE; v.z *= XSCALE; v.w *= XSCALE;
            ss += v.x * v.x + v.y * v.y + v.z * v.z + v.w * v.w;
            __half hx = __float2half_rn(v.x), hy = __float2half_rn(v.y);
            __half hz = __float2half_rn(v.z), hw = __float2half_rn(v.w);
            ((__half2*)(ah + q * 4))[0] = __halves2half2(hx, hy);
            ((__half2*)(ah + q * 4))[1] = __halves2half2(hz, hw);
            ((__half2*)(al + q * 4))[0] = __floats2half2_rn(v.x - __half2float(hx),
                                                            v.y - __half2float(hy));
            ((__half2*)(al + q * 4))[1] = __floats2half2_rn(v.z - __half2float(hz),
                                                            v.w - __half2float(hw));
        }
        ss += __shfl_xor_sync(0xffffffffu, ss, 1);
        ss += __shfl_xor_sync(0xffffffffu, ss, 2);
        if (j == 0) hsm[r] = 0.5f * ss;
    }
#pragma unroll
    for (int it = 0; it < 8; it++) {             // 4096 uint4 of Whi
        int i = it * 512 + tid;
        int rr = i >> 5, q = i & 31;
        *(uint4*)(Bhi + rr * PHI_LDB + q * 8) = ((const uint4*)g_Whi)[i];
    }
    __syncthreads();

    const int wr = warp >> 2, wc = warp & 3;
    wmma::fragment<wmma::accumulator, 16, 16, 16, float> c[2][4];
#pragma unroll
    for (int i = 0; i < 2; i++)
#pragma unroll
        for (int j = 0; j < 4; j++) wmma::fill_fragment(c[i][j], 0.f);

#pragma unroll
    for (int ks = 0; ks < 8; ks++) {
        int kk = ks * 16;
        wmma::fragment<wmma::matrix_a, 16, 16, 16, __half, wmma::row_major> ah[2], al[2];
        wmma::fragment<wmma::matrix_b, 16, 16, 16, __half, wmma::row_major> bh[4];
#pragma unroll
        for (int i = 0; i < 2; i++) {
            wmma::load_matrix_sync(ah[i], Ahi + (wr * 32 + i * 16) * PHI_LDA + kk, PHI_LDA);
            wmma::load_matrix_sync(al[i], Alo + (wr * 32 + i * 16) * PHI_LDA + kk, PHI_LDA);
        }
#pragma unroll
        for (int j = 0; j < 4; j++)
            wmma::load_matrix_sync(bh[j], Bhi + kk * PHI_LDB + wc * 64 + j * 16, PHI_LDB);
#pragma unroll
        for (int i = 0; i < 2; i++)
#pragma unroll
            for (int j = 0; j < 4; j++) {
                wmma::mma_sync(c[i][j], ah[i], bh[j], c[i][j]);
                wmma::mma_sync(c[i][j], al[i], bh[j], c[i][j]);
            }
    }
    __syncthreads();

    if (isq) {
#pragma unroll
        for (int i = 0; i < 2; i++)
#pragma unroll
            for (int j = 0; j < 4; j++)
                wmma::store_matrix_sync(Cs + (wr * 32 + i * 16) * PHI_LDC + wc * 64 + j * 16,
                                        c[i][j], PHI_LDC, wmma::mem_row_major);
        __syncthreads();
#pragma unroll
        for (int rr = 0; rr < 8; rr++) {
            int row = warp * 8 + rr;
            float mx = -INFINITY;
#pragma unroll
            for (int cc = lane; cc < M; cc += 32) mx = fmaxf(mx, Cs[row * PHI_LDC + cc]);
#pragma unroll
            for (int o = 16; o > 0; o >>= 1) mx = fmaxf(mx, __shfl_xor_sync(0xffffffffu, mx, o));
            if (lane == 0) mxs[row] = mx;
        }
        __syncthreads();
#pragma unroll
        for (int it = 0; it < 32; it++) {
            int i = it * 512 + tid;
            int row = i >> 7, c2 = i & 127;
            float hm = hsm[row] + mxs[row];
            float2 u = *(const float2*)&Cs[row * PHI_LDC + c2 * 2];
            float a = (__expf(u.x - hm) + EPS_PHI) * (INV_SQRT_M * QSCALE);
            float b = (__expf(u.y - hm) + EPS_PHI) * (INV_SQRT_M * QSCALE);
            ((__half2*)g_Qh)[(size_t)(row0 + row) * (M / 2) + c2] = __floats2half2_rn(a, b);
        }
    } else {
        float bm = -INFINITY;
#pragma unroll
        for (int i = 0; i < 2; i++)
#pragma unroll
            for (int j = 0; j < 4; j++)
#pragma unroll
                for (int e = 0; e < c[i][j].num_elements; e++)
                    bm = fmaxf(bm, c[i][j].x[e]);
#pragma unroll
        for (int o = 16; o > 0; o >>= 1) bm = fmaxf(bm, __shfl_xor_sync(0xffffffffu, bm, o));
        if (lane == 0) mxs[warp] = bm;
        __syncthreads();
#pragma unroll
        for (int i = 0; i < 2; i++)
#pragma unroll
            for (int j = 0; j < 4; j++)
                wmma::store_matrix_sync(Cs + (wr * 32 + i * 16) * PHI_LDC + wc * 64 + j * 16,
                                        c[i][j], PHI_LDC, wmma::mem_row_major);
        float bmax = mxs[0];
#pragma unroll
        for (int w = 1; w < 16; w++) bmax = fmaxf(bmax, mxs[w]);
        __syncthreads();
        float2 es = make_float2(0.f, 0.f);
#pragma unroll
        for (int it = 0; it < 32; it++) {
            int i = it * 512 + tid;
            int row = i >> 7, c2 = i & 127;
            float hm = hsm[row] + bmax;
            float2 u = *(const float2*)&Cs[row * PHI_LDC + c2 * 2];
            float a = __expf(u.x - hm) * ESCALE;
            float b = __expf(u.y - hm) * ESCALE;
            es.x += a; es.y += b;
            ((__half2*)g_Ke)[(size_t)(row0 + row) * (M / 2) + c2] = __floats2half2_rn(a, b);
        }
        esb[tid] = es;
        __syncthreads();
        if (tid < 128) {
            float2 t0 = esb[tid], t1 = esb[tid + 128];
            float2 t2 = esb[tid + 256], t3 = esb[tid + 384];
            g_esum[tile * M + tid * 2]     = t0.x + t1.x + t2.x + t3.x;
            g_esum[tile * M + tid * 2 + 1] = t0.y + t1.y + t2.y + t3.y;
        }
        if (tid == 0) {
            g_bmax[tile] = bmax;
            atomicMaxF(&g_segmax[tile >> 2], bmax);
        }
    }
}

// ---------------- fused segment kernel ---------------------------------------
#define LDA 264
#define LDB 136
#define LDC 132
#define KVS_OFF 0          // half [256][136] = 69632
#define ST_OFF  69632      // phase1: 2 x (A 33792 + B 17408) = 102400 (..172032)
#define ST_SZ   51200
#define AS2_OFF 69632      // phase2: 2 x half[64][264] = 67584 (..137216)
#define AS2_SZ  33792
#define CS_OFF  137216     // 2 x f32[64][132] = 67584 (..204800)
#define CS_SZ   33792
#define KSM_OFF 204800
#define NORM_OFF 205824
#define QSUM_OFF 206080
#define VSUM_OFF 206336
#define SMEMF   206848

__global__ __launch_bounds__(512, 1) void fused_kernel(const float* __restrict__ V,
                                                       float* __restrict__ out) {
    extern __shared__ char smraw[];
    __half* KVs  = (__half*)smraw;
    float*  ksm  = (float*)(smraw + KSM_OFF);
    float*  normbuf = (float*)(smraw + NORM_OFF);
    float*  qsumbuf = (float*)(smraw + QSUM_OFF);
    float*  vsum = (float*)(smraw + VSUM_OFF);
    const uint32_t sbase = (uint32_t)__cvta_generic_to_shared(smraw);

    const int tid = threadIdx.x, warp = tid >> 5;
    const int vh = blockIdx.x, b = blockIdx.y;

    const float sgm = g_segmax[b];
    if (tid < M) {
        float s = 0.f;
#pragma unroll
        for (int cb = 0; cb < 4; cb++)
            s += __expf(g_bmax[b * 4 + cb] - sgm) * g_esum[(b * 4 + cb) * M + tid];
        ksm[tid] = (s * (1.f / ESCALE) + NP * EPS_PHI) * (INV_SQRT_M * KSCALE);
    }
    if (tid < 128) vsum[tid] = 0.f;

    float corrf[4];
#pragma unroll
    for (int cb = 0; cb < 4; cb++)
        corrf[cb] = __expf(g_bmax[b * 4 + cb] - sgm) * (INV_SQRT_M * KSCALE / ESCALE);

    const __half* Ke = g_Ke + (size_t)b * NP * M;
    const float*  Vb = V    + (size_t)b * NP * DV + vh * 128;

    // ================= PHASE 1: KV-half into smem =================
    const int wr = warp & 7, wv = warp >> 3;

    auto copyA = [&](int s, int ch) {
        uint32_t abase = sbase + ST_OFF + s * ST_SZ;
        const __half* src = Ke + (size_t)(ch * 64) * M;
#pragma unroll
        for (int u = 0; u < 4; u++) {
            int i = tid + u * 512, t = i >> 5, q = i & 31;
            cp16(abase + (t * LDA + q * 8) * 2, src + (size_t)t * M + q * 8);
        }
        asm volatile("cp.async.commit_group;");
    };

    float4 Breg[4], Breg2[4];
    auto loadB = [&](float4* rg, int ch) {
        const float* src = Vb + (size_t)(ch * 64) * DV;
#pragma unroll
        for (int u = 0; u < 4; u++) {
            int i = tid + u * 512, t = i >> 5, q = i & 31;
            rg[u] = ((const float4*)(src + (size_t)t * DV))[q];
        }
    };
    float4 vpart = make_float4(0.f, 0.f, 0.f, 0.f);
    auto storeB = [&](const float4* rg, int s, float cf) {
        __half* Bs = (__half*)(smraw + ST_OFF + s * ST_SZ + 33792);
#pragma unroll
        for (int u = 0; u < 4; u++) {
            int i = tid + u * 512, t = i >> 5, q = i & 31;
            float4 f = rg[u];
            vpart.x += f.x; vpart.y += f.y; vpart.z += f.z; vpart.w += f.w;
            ((__half2*)(Bs + t * LDB))[q * 2]     = __floats2half2_rn(f.x * cf, f.y * cf);
            ((__half2*)(Bs + t * LDB))[q * 2 + 1] = __floats2half2_rn(f.z * cf, f.w * cf);
        }
    };

    wmma::fragment<wmma::accumulator, 16, 16, 16, float> c1[2][4];
#pragma unroll
    for (int i = 0; i < 2; i++)
#pragma unroll
        for (int j = 0; j < 4; j++) wmma::fill_fragment(c1[i][j], 0.f);

    copyA(0, 0);
    loadB(Breg, 0);

    for (int ch = 0; ch < 8; ch++) {
        int s = ch & 1;
        if (ch < 7) copyA(s ^ 1, ch + 1);
        if (ch < 7) asm volatile("cp.async.wait_group 1;");
        else        asm volatile("cp.async.wait_group 0;");
        storeB(Breg, s, corrf[ch >> 1]);
        __syncthreads();
        if (ch < 7) loadB(Breg2, ch + 1);

        const __half* As = (const __half*)(smraw + ST_OFF + s * ST_SZ);
        const __half* Bs = As + 33792 / 2;
#pragma unroll
        for (int kk = 0; kk < 64; kk += 16) {
            wmma::fragment<wmma::matrix_a, 16, 16, 16, __half, wmma::col_major> a[2];
#pragma unroll
            for (int i = 0; i < 2; i++)
                wmma::load_matrix_sync(a[i], As + kk * LDA + wr * 32 + i * 16, LDA);
#pragma unroll
            for (int j = 0; j < 4; j++) {
                wmma::fragment<wmma::matrix_b, 16, 16, 16, __half, wmma::row_major> bf;
                wmma::load_matrix_sync(bf, Bs + kk * LDB + wv * 64 + j * 16, LDB);
#pragma unroll
                for (int i = 0; i < 2; i++)
                    wmma::mma_sync(c1[i][j], a[i], bf, c1[i][j]);
            }
        }
        __syncthreads();
#pragma unroll
        for (int u = 0; u < 4; u++) Breg[u] = Breg2[u];
    }

    // phase-2 chunk-0 A prefetch (ST region now free)
    {
        uint32_t abase = sbase + AS2_OFF;
        const __half* src = g_Qh + (size_t)b * NP * M;
#pragma unroll
        for (int u = 0; u < 4; u++) {
            int i = tid + u * 512, t = i >> 5, q = i & 31;
            cp16(abase + (t * LDA + q * 8) * 2, src + (size_t)t * M + q * 8);
        }
        asm volatile("cp.async.commit_group;");
    }

    {
        int q = tid & 31;
        atomicAdd(&vsum[q * 4 + 0], vpart.x);
        atomicAdd(&vsum[q * 4 + 1], vpart.y);
        atomicAdd(&vsum[q * 4 + 2], vpart.z);
        atomicAdd(&vsum[q * 4 + 3], vpart.w);
    }
#pragma unroll
    for (int i = 0; i < 2; i++)
#pragma unroll
        for (int j = 0; j < 4; j++) {
            wmma::fragment<wmma::accumulator, 16, 16, 16, __half> hf;
#pragma unroll
            for (int e = 0; e < hf.num_elements; e++)
                hf.x[e] = __float2half_rn(c1[i][j].x[e]);
            wmma::store_matrix_sync(KVs + (wr * 32 + i * 16) * LDB + wv * 64 + j * 16,
                                    hf, LDB, wmma::mem_row_major);
        }

    // ================= PHASE 2: 8 pipelined 64-token chunks =================
    const int kh  = warp >> 3;          // k half
    const int pos = warp & 7;
    const int tr  = pos >> 2;           // token tile (2 x 32)
    const int vc  = pos & 3;            // v tile (4 x 32)
    const __half* Qh = g_Qh + (size_t)b * NP * M;
    float* CsK = (float*)(smraw + CS_OFF + kh * CS_SZ);
    const float* Cs0 = (const float*)(smraw + CS_OFF);
    const float* Cs1 = (const float*)(smraw + CS_OFF + CS_SZ);

    for (int c = 0; c < 8; c++) {
        int s = c & 1;
        asm volatile("cp.async.wait_group 0;");
        __syncthreads();   // As2 stage s ready; KVs ready (c==0); Cs consumed (c>0)

        if (c < 7) {       // prefetch next chunk into s^1, flies during MMA
            uint32_t abase = sbase + AS2_OFF + (s ^ 1) * AS2_SZ;
            const __half* src = Qh + (size_t)((c + 1) * 64) * M;
#pragma unroll
            for (int u = 0; u < 4; u++) {
                int i = tid + u * 512, t = i >> 5, q = i & 31;
                cp16(abase + (t * LDA + q * 8) * 2, src + (size_t)t * M + q * 8);
            }
            asm volatile("cp.async.commit_group;");
        }

        const __half* As2 = (const __half*)(smraw + AS2_OFF + s * AS2_SZ);
        {   // fused norm + qsum: 8 threads per row, 32 m each
            int row = tid >> 3, q8 = tid & 7;
            const __half2* qrow = (const __half2*)(As2 + row * LDA + q8 * 32);
            const float* kk2 = ksm + q8 * 32;
            float np = 0.f, qs = 0.f;
#pragma unroll
            for (int mm = 0; mm < 16; mm++) {
                float2 q2 = __half22float2(qrow[mm]);
                np += q2.x * kk2[mm * 2] + q2.y * kk2[mm * 2 + 1];
                qs += q2.x + q2.y;
            }
#pragma unroll
            for (int o = 4; o > 0; o >>= 1) {
                np += __shfl_xor_sync(0xffffffffu, np, o);
                qs += __shfl_xor_sync(0xffffffffu, qs, o);
            }
            if (q8 == 0) { normbuf[row] = np; qsumbuf[row] = qs; }
        }

        wmma::fragment<wmma::accumulator, 16, 16, 16, float> c2[2][2];
#pragma unroll
        for (int i = 0; i < 2; i++)
#pragma unroll
            for (int j = 0; j < 2; j++) wmma::fill_fragment(c2[i][j], 0.f);

#pragma unroll
        for (int ks = 0; ks < 8; ks++) {
            int kk = kh * 128 + ks * 16;
            wmma::fragment<wmma::matrix_a, 16, 16, 16, __half, wmma::row_major> a[2];
            wmma::fragment<wmma::matrix_b, 16, 16, 16, __half, wmma::row_major> bf[2];
#pragma unroll
            for (int i = 0; i < 2; i++)
                wmma::load_matrix_sync(a[i], As2 + (tr * 32 + i * 16) * LDA + kk, LDA);
#pragma unroll
            for (int j = 0; j < 2; j++)
                wmma::load_matrix_sync(bf[j], KVs + kk * LDB + vc * 32 + j * 16, LDB);
#pragma unroll
            for (int i = 0; i < 2; i++)
#pragma unroll
                for (int j = 0; j < 2; j++)
                    wmma::mma_sync(c2[i][j], a[i], bf[j], c2[i][j]);
        }
#pragma unroll
        for (int i = 0; i < 2; i++)
#pragma unroll
            for (int j = 0; j < 2; j++)
                wmma::store_matrix_sync(CsK + (tr * 32 + i * 16) * LDC + vc * 32 + j * 16,
                                        c2[i][j], LDC, wmma::mem_row_major);
        __syncthreads();

        float* op = out + ((size_t)(b * NP + c * 64)) * DV + vh * 128;
#pragma unroll
        for (int it = 0; it < 8; it++) {
            int i = it * 512 + tid;
            int e = i * 2, r = e >> 7, cc = e & 127;
            float inv = 1.0f / (normbuf[r] + NORM_EPS);
            float q1 = qsumbuf[r] * C2F;
            float2 v;
            v.x = (Cs0[r * LDC + cc]     + Cs1[r * LDC + cc]     + q1 * vsum[cc])     * inv;
            v.y = (Cs0[r * LDC + cc + 1] + Cs1[r * LDC + cc + 1] + q1 * vsum[cc + 1]) * inv;
            *(float2*)(op + (size_t)r * DV + cc) = v;
        }
    }
}

// ---------------- launch ------------------------------------------------------
extern "C" void kernel_launch(void* const* d_in, const int* in_sizes, int n_in,
                              void* d_out, int out_size) {
    const float* Q     = (const float*)d_in[0];
    const float* K     = (const float*)d_in[1];
    const float* V     = (const float*)d_in[2];
    const float* omega = (const float*)d_in[3];
    float* out = (float*)d_out;

    cudaFuncSetAttribute(phi_wmma_kernel, cudaFuncAttributeMaxDynamicSharedMemorySize, PHI_SMEM);
    cudaFuncSetAttribute(fused_kernel,    cudaFuncAttributeMaxDynamicSharedMemorySize, SMEMF);

    omega_split_kernel<<<(D * M) / 256, 256>>>(omega);
    phi_wmma_kernel<<<2 * (N_TOK / 128), 512, PHI_SMEM>>>(Q, K);
    fused_kernel<<<dim3(2, NB), 512, SMEMF>>>(V, out);
}

// round 10
// speedup vs baseline: 1.1965x; 1.1158x over previous
#include <cuda_runtime.h>
#include <cuda_fp16.h>
#include <mma.h>
#include <math.h>
#include <stdint.h>

using namespace nvcuda;

#define N_TOK 32768
#define NB 64
#define NP 512
#define D 128
#define M 256
#define DV 256
#define EPS_PHI 1e-4f
#define EPS_NORM 1e-8f
#define INV_SQRT_M 0.0625f
#define XSCALE 0.29730177875068026f   // 1/128^0.25
#define KSCALE 256.0f
#define QSCALE 256.0f
#define ESCALE 512.0f
#define C2F (EPS_PHI * INV_SQRT_M * KSCALE)
#define NORM_EPS (EPS_NORM * KSCALE * QSCALE)

// ---------------- scratch ------------------------------------------------------
__device__ float  g_bmax[N_TOK / 128];
__device__ float  g_esum[(N_TOK / 128) * M];
__device__ __align__(16) __half g_Qh[N_TOK * M];
__device__ __align__(16) __half g_Ke[N_TOK * M];

__device__ __forceinline__ void cp16(uint32_t dst, const void* src) {
    asm volatile("cp.async.cg.shared.global [%0], [%1], 16;" :: "r"(dst), "l"(src));
}

// ---------------- phi: U = Xhi@Whi (fp16 MMA, fp32 accum) --------------------
#define PHI_LDA 136
#define PHI_LDB 264
#define PHI_LDC 260
#define PHI_SMEM 138240

__global__ __launch_bounds__(512, 1) void phi_wmma_kernel(
    const float* __restrict__ Q, const float* __restrict__ K,
    const float* __restrict__ omega) {
    extern __shared__ char smraw[];
    __half* Ahi = (__half*)smraw;
    __half* Bhi = (__half*)(smraw + 34816);
    float*  Cs  = (float*)smraw;
    float*  hsm = (float*)(smraw + 133120);
    float*  mxs = (float*)(smraw + 133632);
    float2* esb = (float2*)(smraw + 134144);

    const int tid  = threadIdx.x;
    const int warp = tid >> 5, lane = tid & 31;
    const bool isq = blockIdx.x < (N_TOK / 128);
    const int tile = isq ? blockIdx.x : blockIdx.x - (N_TOK / 128);
    const int row0 = tile * 128;
    const float* X = isq ? Q : K;

    // ---- load X (scaled) -> Ahi, h per row ----
    {
        int r = tid >> 2, j = tid & 3;
        const float4* src = (const float4*)(X + (size_t)(row0 + r) * D + j * 32);
        __half* ah = Ahi + r * PHI_LDA + j * 32;
        float ss = 0.f;
#pragma unroll
        for (int q = 0; q < 8; q++) {
            float4 v = src[q];
            v.x *= XSCALE; v.y *= XSCALE; v.z *= XSCALE; v.w *= XSCALE;
            ss += v.x * v.x + v.y * v.y + v.z * v.z + v.w * v.w;
            ((__half2*)(ah + q * 4))[0] = __floats2half2_rn(v.x, v.y);
            ((__half2*)(ah + q * 4))[1] = __floats2half2_rn(v.z, v.w);
        }
        ss += __shfl_xor_sync(0xffffffffu, ss, 1);
        ss += __shfl_xor_sync(0xffffffffu, ss, 2);
        if (j == 0) hsm[r] = 0.5f * ss;
    }
    // ---- convert omega fp32 -> Bhi fp16 (FULL 8192 float4 = 32768 floats) ----
#pragma unroll
    for (int it = 0; it < 16; it++) {
        int i = it * 512 + tid;                  // 8192 float4 total
        int rr = i >> 6, c4 = i & 63;
        float4 v = ((const float4*)omega)[i];
        __half* bh = Bhi + rr * PHI_LDB + c4 * 4;
        ((__half2*)bh)[0] = __floats2half2_rn(v.x, v.y);
        ((__half2*)bh)[1] = __floats2half2_rn(v.z, v.w);
    }
    __syncthreads();

    const int wr = warp >> 2, wc = warp & 3;
    wmma::fragment<wmma::accumulator, 16, 16, 16, float> c[2][4];
#pragma unroll
    for (int i = 0; i < 2; i++)
#pragma unroll
        for (int j = 0; j < 4; j++) wmma::fill_fragment(c[i][j], 0.f);

#pragma unroll
    for (int ks = 0; ks < 8; ks++) {
        int kk = ks * 16;
        wmma::fragment<wmma::matrix_a, 16, 16, 16, __half, wmma::row_major> ah[2];
        wmma::fragment<wmma::matrix_b, 16, 16, 16, __half, wmma::row_major> bh[4];
#pragma unroll
        for (int i = 0; i < 2; i++)
            wmma::load_matrix_sync(ah[i], Ahi + (wr * 32 + i * 16) * PHI_LDA + kk, PHI_LDA);
#pragma unroll
        for (int j = 0; j < 4; j++)
            wmma::load_matrix_sync(bh[j], Bhi + kk * PHI_LDB + wc * 64 + j * 16, PHI_LDB);
#pragma unroll
        for (int i = 0; i < 2; i++)
#pragma unroll
            for (int j = 0; j < 4; j++)
                wmma::mma_sync(c[i][j], ah[i], bh[j], c[i][j]);
    }
    __syncthreads();

    if (isq) {
#pragma unroll
        for (int i = 0; i < 2; i++)
#pragma unroll
            for (int j = 0; j < 4; j++)
                wmma::store_matrix_sync(Cs + (wr * 32 + i * 16) * PHI_LDC + wc * 64 + j * 16,
                                        c[i][j], PHI_LDC, wmma::mem_row_major);
        __syncthreads();
#pragma unroll
        for (int rr = 0; rr < 8; rr++) {
            int row = warp * 8 + rr;
            float mx = -INFINITY;
#pragma unroll
            for (int cc = lane; cc < M; cc += 32) mx = fmaxf(mx, Cs[row * PHI_LDC + cc]);
#pragma unroll
            for (int o = 16; o > 0; o >>= 1) mx = fmaxf(mx, __shfl_xor_sync(0xffffffffu, mx, o));
            if (lane == 0) mxs[row] = mx;
        }
        __syncthreads();
#pragma unroll
        for (int it = 0; it < 32; it++) {
            int i = it * 512 + tid;
            int row = i >> 7, c2 = i & 127;
            float hm = hsm[row] + mxs[row];
            float2 u = *(const float2*)&Cs[row * PHI_LDC + c2 * 2];
            float a = (__expf(u.x - hm) + EPS_PHI) * (INV_SQRT_M * QSCALE);
            float b = (__expf(u.y - hm) + EPS_PHI) * (INV_SQRT_M * QSCALE);
            ((__half2*)g_Qh)[(size_t)(row0 + row) * (M / 2) + c2] = __floats2half2_rn(a, b);
        }
    } else {
        float bm = -INFINITY;
#pragma unroll
        for (int i = 0; i < 2; i++)
#pragma unroll
            for (int j = 0; j < 4; j++)
#pragma unroll
                for (int e = 0; e < c[i][j].num_elements; e++)
                    bm = fmaxf(bm, c[i][j].x[e]);
#pragma unroll
        for (int o = 16; o > 0; o >>= 1) bm = fmaxf(bm, __shfl_xor_sync(0xffffffffu, bm, o));
        if (lane == 0) mxs[warp] = bm;
        __syncthreads();
#pragma unroll
        for (int i = 0; i < 2; i++)
#pragma unroll
            for (int j = 0; j < 4; j++)
                wmma::store_matrix_sync(Cs + (wr * 32 + i * 16) * PHI_LDC + wc * 64 + j * 16,
                                        c[i][j], PHI_LDC, wmma::mem_row_major);
        float bmax = mxs[0];
#pragma unroll
        for (int w = 1; w < 16; w++) bmax = fmaxf(bmax, mxs[w]);
        __syncthreads();
        float2 es = make_float2(0.f, 0.f);
#pragma unroll
        for (int it = 0; it < 32; it++) {
            int i = it * 512 + tid;
            int row = i >> 7, c2 = i & 127;
            float hm = hsm[row] + bmax;
            float2 u = *(const float2*)&Cs[row * PHI_LDC + c2 * 2];
            float a = __expf(u.x - hm) * ESCALE;
            float b = __expf(u.y - hm) * ESCALE;
            es.x += a; es.y += b;
            ((__half2*)g_Ke)[(size_t)(row0 + row) * (M / 2) + c2] = __floats2half2_rn(a, b);
        }
        esb[tid] = es;
        __syncthreads();
        if (tid < 128) {
            float2 t0 = esb[tid], t1 = esb[tid + 128];
            float2 t2 = esb[tid + 256], t3 = esb[tid + 384];
            g_esum[tile * M + tid * 2]     = t0.x + t1.x + t2.x + t3.x;
            g_esum[tile * M + tid * 2 + 1] = t0.y + t1.y + t2.y + t3.y;
        }
        if (tid == 0) g_bmax[tile] = bmax;
    }
}

// ---------------- fused segment kernel ---------------------------------------
#define LDA 264
#define LDB 136
#define LDC 132
#define KVS_OFF 0
#define ST_OFF  69632
#define ST_SZ   51200
#define AS2_OFF 69632
#define AS2_SZ  33792
#define CS_OFF  137216
#define CS_SZ   33792
#define KSM_OFF 204800
#define NORM_OFF 205824
#define QSUM_OFF 206080
#define VSUM_OFF 206336
#define SMEMF   206848

__global__ __launch_bounds__(512, 1) void fused_kernel(const float* __restrict__ V,
                                                       float* __restrict__ out) {
    extern __shared__ char smraw[];
    __half* KVs  = (__half*)smraw;
    float*  ksm  = (float*)(smraw + KSM_OFF);
    float*  normbuf = (float*)(smraw + NORM_OFF);
    float*  qsumbuf = (float*)(smraw + QSUM_OFF);
    float*  vsum = (float*)(smraw + VSUM_OFF);
    const uint32_t sbase = (uint32_t)__cvta_generic_to_shared(smraw);

    const int tid = threadIdx.x, warp = tid >> 5;
    const int vh = blockIdx.x, b = blockIdx.y;

    float bm4[4];
#pragma unroll
    for (int cb = 0; cb < 4; cb++) bm4[cb] = g_bmax[b * 4 + cb];
    const float sgm = fmaxf(fmaxf(bm4[0], bm4[1]), fmaxf(bm4[2], bm4[3]));

    if (tid < M) {
        float s = 0.f;
#pragma unroll
        for (int cb = 0; cb < 4; cb++)
            s += __expf(bm4[cb] - sgm) * g_esum[(b * 4 + cb) * M + tid];
        ksm[tid] = (s * (1.f / ESCALE) + NP * EPS_PHI) * (INV_SQRT_M * KSCALE);
    }
    if (tid < 128) vsum[tid] = 0.f;

    float corrf[4];
#pragma unroll
    for (int cb = 0; cb < 4; cb++)
        corrf[cb] = __expf(bm4[cb] - sgm) * (INV_SQRT_M * KSCALE / ESCALE);

    const __half* Ke = g_Ke + (size_t)b * NP * M;
    const float*  Vb = V    + (size_t)b * NP * DV + vh * 128;

    // ================= PHASE 1 =================
    const int wr = warp & 7, wv = warp >> 3;

    auto copyA = [&](int s, int ch) {
        uint32_t abase = sbase + ST_OFF + s * ST_SZ;
        const __half* src = Ke + (size_t)(ch * 64) * M;
#pragma unroll
        for (int u = 0; u < 4; u++) {
            int i = tid + u * 512, t = i >> 5, q = i & 31;
            cp16(abase + (t * LDA + q * 8) * 2, src + (size_t)t * M + q * 8);
        }
        asm volatile("cp.async.commit_group;");
    };

    float4 Breg[4], Breg2[4];
    auto loadB = [&](float4* rg, int ch) {
        const float* src = Vb + (size_t)(ch * 64) * DV;
#pragma unroll
        for (int u = 0; u < 4; u++) {
            int i = tid + u * 512, t = i >> 5, q = i & 31;
            rg[u] = ((const float4*)(src + (size_t)t * DV))[q];
        }
    };
    float4 vpart = make_float4(0.f, 0.f, 0.f, 0.f);
    auto storeB = [&](const float4* rg, int s, float cf) {
        __half* Bs = (__half*)(smraw + ST_OFF + s * ST_SZ + 33792);
#pragma unroll
        for (int u = 0; u < 4; u++) {
            int i = tid + u * 512, t = i >> 5, q = i & 31;
            float4 f = rg[u];
            vpart.x += f.x; vpart.y += f.y; vpart.z += f.z; vpart.w += f.w;
            ((__half2*)(Bs + t * LDB))[q * 2]     = __floats2half2_rn(f.x * cf, f.y * cf);
            ((__half2*)(Bs + t * LDB))[q * 2 + 1] = __floats2half2_rn(f.z * cf, f.w * cf);
        }
    };

    wmma::fragment<wmma::accumulator, 16, 16, 16, float> c1[2][4];
#pragma unroll
    for (int i = 0; i < 2; i++)
#pragma unroll
        for (int j = 0; j < 4; j++) wmma::fill_fragment(c1[i][j], 0.f);

    copyA(0, 0);
    loadB(Breg, 0);

    for (int ch = 0; ch < 8; ch++) {
        int s = ch & 1;
        if (ch < 7) copyA(s ^ 1, ch + 1);
        if (ch < 7) asm volatile("cp.async.wait_group 1;");
        else        asm volatile("cp.async.wait_group 0;");
        storeB(Breg, s, corrf[ch >> 1]);
        __syncthreads();
        if (ch < 7) loadB(Breg2, ch + 1);

        const __half* As = (const __half*)(smraw + ST_OFF + s * ST_SZ);
        const __half* Bs = As + 33792 / 2;
#pragma unroll
        for (int kk = 0; kk < 64; kk += 16) {
            wmma::fragment<wmma::matrix_a, 16, 16, 16, __half, wmma::col_major> a[2];
#pragma unroll
            for (int i = 0; i < 2; i++)
                wmma::load_matrix_sync(a[i], As + kk * LDA + wr * 32 + i * 16, LDA);
#pragma unroll
            for (int j = 0; j < 4; j++) {
                wmma::fragment<wmma::matrix_b, 16, 16, 16, __half, wmma::row_major> bf;
                wmma::load_matrix_sync(bf, Bs + kk * LDB + wv * 64 + j * 16, LDB);
#pragma unroll
                for (int i = 0; i < 2; i++)
                    wmma::mma_sync(c1[i][j], a[i], bf, c1[i][j]);
            }
        }
        __syncthreads();
#pragma unroll
        for (int u = 0; u < 4; u++) Breg[u] = Breg2[u];
    }

    {
        uint32_t abase = sbase + AS2_OFF;
        const __half* src = g_Qh + (size_t)b * NP * M;
#pragma unroll
        for (int u = 0; u < 4; u++) {
            int i = tid + u * 512, t = i >> 5, q = i & 31;
            cp16(abase + (t * LDA + q * 8) * 2, src + (size_t)t * M + q * 8);
        }
        asm volatile("cp.async.commit_group;");
    }

    {
        int q = tid & 31;
        atomicAdd(&vsum[q * 4 + 0], vpart.x);
        atomicAdd(&vsum[q * 4 + 1], vpart.y);
        atomicAdd(&vsum[q * 4 + 2], vpart.z);
        atomicAdd(&vsum[q * 4 + 3], vpart.w);
    }
#pragma unroll
    for (int i = 0; i < 2; i++)
#pragma unroll
        for (int j = 0; j < 4; j++) {
            wmma::fragment<wmma::accumulator, 16, 16, 16, __half> hf;
#pragma unroll
            for (int e = 0; e < hf.num_elements; e++)
                hf.x[e] = __float2half_rn(c1[i][j].x[e]);
            wmma::store_matrix_sync(KVs + (wr * 32 + i * 16) * LDB + wv * 64 + j * 16,
                                    hf, LDB, wmma::mem_row_major);
        }

    // ================= PHASE 2 =================
    const int kh  = warp >> 3;
    const int pos = warp & 7;
    const int tr  = pos >> 2;
    const int vc  = pos & 3;
    const __half* Qh = g_Qh + (size_t)b * NP * M;
    float* CsK = (float*)(smraw + CS_OFF + kh * CS_SZ);
    const float* Cs0 = (const float*)(smraw + CS_OFF);
    const float* Cs1 = (const float*)(smraw + CS_OFF + CS_SZ);

    for (int c = 0; c < 8; c++) {
        int s = c & 1;
        asm volatile("cp.async.wait_group 0;");
        __syncthreads();

        if (c < 7) {
            uint32_t abase = sbase + AS2_OFF + (s ^ 1) * AS2_SZ;
            const __half* src = Qh + (size_t)((c + 1) * 64) * M;
#pragma unroll
            for (int u = 0; u < 4; u++) {
                int i = tid + u * 512, t = i >> 5, q = i & 31;
                cp16(abase + (t * LDA + q * 8) * 2, src + (size_t)t * M + q * 8);
            }
            asm volatile("cp.async.commit_group;");
        }

        const __half* As2 = (const __half*)(smraw + AS2_OFF + s * AS2_SZ);
        {
            int row = tid >> 3, q8 = tid & 7;
            const __half2* qrow = (const __half2*)(As2 + row * LDA + q8 * 32);
            const float* kk2 = ksm + q8 * 32;
            float np = 0.f, qs = 0.f;
#pragma unroll
            for (int mm = 0; mm < 16; mm++) {
                float2 q2 = __half22float2(qrow[mm]);
                np += q2.x * kk2[mm * 2] + q2.y * kk2[mm * 2 + 1];
                qs += q2.x + q2.y;
            }
#pragma unroll
            for (int o = 4; o > 0; o >>= 1) {
                np += __shfl_xor_sync(0xffffffffu, np, o);
                qs += __shfl_xor_sync(0xffffffffu, qs, o);
            }
            if (q8 == 0) { normbuf[row] = np; qsumbuf[row] = qs; }
        }

        wmma::fragment<wmma::accumulator, 16, 16, 16, float> c2[2][2];
#pragma unroll
        for (int i = 0; i < 2; i++)
#pragma unroll
            for (int j = 0; j < 2; j++) wmma::fill_fragment(c2[i][j], 0.f);

#pragma unroll
        for (int ks = 0; ks < 8; ks++) {
            int kk = kh * 128 + ks * 16;
            wmma::fragment<wmma::matrix_a, 16, 16, 16, __half, wmma::row_major> a[2];
            wmma::fragment<wmma::matrix_b, 16, 16, 16, __half, wmma::row_major> bf[2];
#pragma unroll
            for (int i = 0; i < 2; i++)
                wmma::load_matrix_sync(a[i], As2 + (tr * 32 + i * 16) * LDA + kk, LDA);
#pragma unroll
            for (int j = 0; j < 2; j++)
                wmma::load_matrix_sync(bf[j], KVs + kk * LDB + vc * 32 + j * 16, LDB);
#pragma unroll
            for (int i = 0; i < 2; i++)
#pragma unroll
                for (int j = 0; j < 2; j++)
                    wmma::mma_sync(c2[i][j], a[i], bf[j], c2[i][j]);
        }
#pragma unroll
        for (int i = 0; i < 2; i++)
#pragma unroll
            for (int j = 0; j < 2; j++)
                wmma::store_matrix_sync(CsK + (tr * 32 + i * 16) * LDC + vc * 32 + j * 16,
                                        c2[i][j], LDC, wmma::mem_row_major);
        __syncthreads();

        float* op = out + ((size_t)(b * NP + c * 64)) * DV + vh * 128;
#pragma unroll
        for (int it = 0; it < 8; it++) {
            int i = it * 512 + tid;
            int e = i * 2, r = e >> 7, cc = e & 127;
            float inv = 1.0f / (normbuf[r] + NORM_EPS);
            float q1 = qsumbuf[r] * C2F;
            float2 v;
            v.x = (Cs0[r * LDC + cc]     + Cs1[r * LDC + cc]     + q1 * vsum[cc])     * inv;
            v.y = (Cs0[r * LDC + cc + 1] + Cs1[r * LDC + cc + 1] + q1 * vsum[cc + 1]) * inv;
            *(float2*)(op + (size_t)r * DV + cc) = v;
        }
    }
}

// ---------------- launch ------------------------------------------------------
extern "C" void kernel_launch(void* const* d_in, const int* in_sizes, int n_in,
                              void* d_out, int out_size) {
    const float* Q     = (const float*)d_in[0];
    const float* K     = (const float*)d_in[1];
    const float* V     = (const float*)d_in[2];
    const float* omega = (const float*)d_in[3];
    float* out = (float*)d_out;

    cudaFuncSetAttribute(phi_wmma_kernel, cudaFuncAttributeMaxDynamicSharedMemorySize, PHI_SMEM);
    cudaFuncSetAttribute(fused_kernel,    cudaFuncAttributeMaxDynamicSharedMemorySize, SMEMF);

    phi_wmma_kernel<<<2 * (N_TOK / 128), 512, PHI_SMEM>>>(Q, K, omega);
    fused_kernel<<<dim3(2, NB), 512, SMEMF>>>(V, out);
}

// round 11
// speedup vs baseline: 1.2364x; 1.0334x over previous
#include <cuda_runtime.h>
#include <cuda_fp16.h>
#include <mma.h>
#include <math.h>
#include <stdint.h>

using namespace nvcuda;

#define N_TOK 32768
#define NB 64
#define NP 512
#define D 128
#define M 256
#define DV 256
#define EPS_PHI 1e-4f
#define EPS_NORM 1e-8f
#define INV_SQRT_M 0.0625f
#define XSCALE 0.29730177875068026f   // 1/128^0.25
#define KSCALE 256.0f
#define QSCALE 256.0f
#define ESCALE 512.0f
#define C2F (EPS_PHI * INV_SQRT_M * KSCALE)
#define NORM_EPS (EPS_NORM * KSCALE * QSCALE)

#define NTILE 64                      // phi tile = 64 tokens
#define NTILES (N_TOK / NTILE)        // 512 per side

// ---------------- scratch ------------------------------------------------------
__device__ float  g_bmax[NTILES];            // per-64-token K-tile max
__device__ float  g_esum[NTILES * M];
__device__ __align__(16) __half g_Qh[N_TOK * M];
__device__ __align__(16) __half g_Ke[N_TOK * M];

__device__ __forceinline__ void cp16(uint32_t dst, const void* src) {
    asm volatile("cp.async.cg.shared.global [%0], [%1], 16;" :: "r"(dst), "l"(src));
}
__device__ __forceinline__ uint32_t h2bits(__half2 h) { return *(uint32_t*)&h; }

// ---------------- phi: U = X@omega (fp16 MMA, fp32 accum) --------------------
// 256 threads, 64 tokens, 2 blocks/SM.
// smem: Ahi [64][136] @0 (17408), Bhi [128][264] @17408 (67584) -> 84992
//       Cs overlay [64][260] f32 @0 (66560)
//       hsm @84992 (256), mxs @85248 (256), esb @85504 (2048) -> 87552
#define PHI_LDA 136
#define PHI_LDB 264
#define PHI_LDC 260
#define PHI_SMEM 87552

__global__ __launch_bounds__(256, 2) void phi_wmma_kernel(
    const float* __restrict__ Q, const float* __restrict__ K,
    const float* __restrict__ omega) {
    extern __shared__ char smraw[];
    __half* Ahi = (__half*)smraw;
    __half* Bhi = (__half*)(smraw + 17408);
    float*  Cs  = (float*)smraw;
    float*  hsm = (float*)(smraw + 84992);
    float*  mxs = (float*)(smraw + 85248);
    float2* esb = (float2*)(smraw + 85504);

    const int tid  = threadIdx.x;
    const int warp = tid >> 5, lane = tid & 31;
    const bool isq = blockIdx.x < NTILES;
    const int tile = isq ? blockIdx.x : blockIdx.x - NTILES;
    const int row0 = tile * NTILE;
    const float* X = isq ? Q : K;

    // ---- load X (scaled) -> Ahi, h per row (4 threads/row) ----
    {
        int r = tid >> 2, j = tid & 3;
        const float4* src = (const float4*)(X + (size_t)(row0 + r) * D + j * 32);
        __half* ah = Ahi + r * PHI_LDA + j * 32;
        float ss = 0.f;
#pragma unroll
        for (int q = 0; q < 8; q++) {
            float4 v = src[q];
            v.x *= XSCALE; v.y *= XSCALE; v.z *= XSCALE; v.w *= XSCALE;
            ss += v.x * v.x + v.y * v.y + v.z * v.z + v.w * v.w;
            uint2 w = make_uint2(h2bits(__floats2half2_rn(v.x, v.y)),
                                 h2bits(__floats2half2_rn(v.z, v.w)));
            *(uint2*)(ah + q * 4) = w;
        }
        ss += __shfl_xor_sync(0xffffffffu, ss, 1);
        ss += __shfl_xor_sync(0xffffffffu, ss, 2);
        if (j == 0) hsm[r] = 0.5f * ss;
    }
    // ---- convert omega fp32 -> Bhi fp16 (8192 float4 total) ----
#pragma unroll
    for (int it = 0; it < 32; it++) {
        int i = it * 256 + tid;
        int rr = i >> 6, c4 = i & 63;
        float4 v = ((const float4*)omega)[i];
        uint2 w = make_uint2(h2bits(__floats2half2_rn(v.x, v.y)),
                             h2bits(__floats2half2_rn(v.z, v.w)));
        *(uint2*)(Bhi + rr * PHI_LDB + c4 * 4) = w;
    }
    __syncthreads();

    // ---- MMA: 8 warps, warp tile 32 tokens x 64 features ----
    const int wr = warp >> 2, wc = warp & 3;
    wmma::fragment<wmma::accumulator, 16, 16, 16, float> c[2][4];
#pragma unroll
    for (int i = 0; i < 2; i++)
#pragma unroll
        for (int j = 0; j < 4; j++) wmma::fill_fragment(c[i][j], 0.f);

#pragma unroll
    for (int ks = 0; ks < 8; ks++) {
        int kk = ks * 16;
        wmma::fragment<wmma::matrix_a, 16, 16, 16, __half, wmma::row_major> ah[2];
        wmma::fragment<wmma::matrix_b, 16, 16, 16, __half, wmma::row_major> bh[4];
#pragma unroll
        for (int i = 0; i < 2; i++)
            wmma::load_matrix_sync(ah[i], Ahi + (wr * 32 + i * 16) * PHI_LDA + kk, PHI_LDA);
#pragma unroll
        for (int j = 0; j < 4; j++)
            wmma::load_matrix_sync(bh[j], Bhi + kk * PHI_LDB + wc * 64 + j * 16, PHI_LDB);
#pragma unroll
        for (int i = 0; i < 2; i++)
#pragma unroll
            for (int j = 0; j < 4; j++)
                wmma::mma_sync(c[i][j], ah[i], bh[j], c[i][j]);
    }
    __syncthreads();   // Ahi/Bhi reads done -> Cs overlay safe

    if (isq) {
#pragma unroll
        for (int i = 0; i < 2; i++)
#pragma unroll
            for (int j = 0; j < 4; j++)
                wmma::store_matrix_sync(Cs + (wr * 32 + i * 16) * PHI_LDC + wc * 64 + j * 16,
                                        c[i][j], PHI_LDC, wmma::mem_row_major);
        __syncthreads();
        // per-row max: warp handles rows warp*8..+8
#pragma unroll
        for (int rr = 0; rr < 8; rr++) {
            int row = warp * 8 + rr;
            float mx = -INFINITY;
#pragma unroll
            for (int cc = lane; cc < M; cc += 32) mx = fmaxf(mx, Cs[row * PHI_LDC + cc]);
#pragma unroll
            for (int o = 16; o > 0; o >>= 1) mx = fmaxf(mx, __shfl_xor_sync(0xffffffffu, mx, o));
            if (lane == 0) mxs[row] = mx;
        }
        __syncthreads();
#pragma unroll
        for (int it = 0; it < 32; it++) {
            int i = it * 256 + tid;
            int row = i >> 7, c2 = i & 127;
            float hm = hsm[row] + mxs[row];
            float2 u = *(const float2*)&Cs[row * PHI_LDC + c2 * 2];
            float a = (__expf(u.x - hm) + EPS_PHI) * (INV_SQRT_M * QSCALE);
            float b = (__expf(u.y - hm) + EPS_PHI) * (INV_SQRT_M * QSCALE);
            ((__half2*)g_Qh)[(size_t)(row0 + row) * (M / 2) + c2] = __floats2half2_rn(a, b);
        }
    } else {
        // tile max from fragments
        float bm = -INFINITY;
#pragma unroll
        for (int i = 0; i < 2; i++)
#pragma unroll
            for (int j = 0; j < 4; j++)
#pragma unroll
                for (int e = 0; e < c[i][j].num_elements; e++)
                    bm = fmaxf(bm, c[i][j].x[e]);
#pragma unroll
        for (int o = 16; o > 0; o >>= 1) bm = fmaxf(bm, __shfl_xor_sync(0xffffffffu, bm, o));
        if (lane == 0) mxs[warp] = bm;
#pragma unroll
        for (int i = 0; i < 2; i++)
#pragma unroll
            for (int j = 0; j < 4; j++)
                wmma::store_matrix_sync(Cs + (wr * 32 + i * 16) * PHI_LDC + wc * 64 + j * 16,
                                        c[i][j], PHI_LDC, wmma::mem_row_major);
        __syncthreads();
        float bmax = mxs[0];
#pragma unroll
        for (int w = 1; w < 8; w++) bmax = fmaxf(bmax, mxs[w]);

        float2 es = make_float2(0.f, 0.f);   // fixed half2 column (tid&127)
#pragma unroll
        for (int it = 0; it < 32; it++) {
            int i = it * 256 + tid;
            int row = i >> 7, c2 = i & 127;
            float hm = hsm[row] + bmax;
            float2 u = *(const float2*)&Cs[row * PHI_LDC + c2 * 2];
            float a = __expf(u.x - hm) * ESCALE;
            float b = __expf(u.y - hm) * ESCALE;
            es.x += a; es.y += b;
            ((__half2*)g_Ke)[(size_t)(row0 + row) * (M / 2) + c2] = __floats2half2_rn(a, b);
        }
        esb[tid] = es;
        __syncthreads();
        if (tid < 128) {
            float2 t0 = esb[tid], t1 = esb[tid + 128];
            g_esum[tile * M + tid * 2]     = t0.x + t1.x;
            g_esum[tile * M + tid * 2 + 1] = t0.y + t1.y;
        }
        if (tid == 0) g_bmax[tile] = bmax;
    }
}

// ---------------- fused segment kernel ---------------------------------------
#define LDA 264
#define LDB 136
#define LDC 132
#define ST_OFF  69632
#define ST_SZ   51200
#define AS2_OFF 69632
#define AS2_SZ  33792
#define CS_OFF  137216
#define CS_SZ   33792
#define KSM_OFF 204800
#define NORM_OFF 205824
#define QSUM_OFF 206080
#define VSUM_OFF 206336
#define SMEMF   206848

__global__ __launch_bounds__(512, 1) void fused_kernel(const float* __restrict__ V,
                                                       float* __restrict__ out) {
    extern __shared__ char smraw[];
    __half* KVs  = (__half*)smraw;
    float*  ksm  = (float*)(smraw + KSM_OFF);
    float*  normbuf = (float*)(smraw + NORM_OFF);
    float*  qsumbuf = (float*)(smraw + QSUM_OFF);
    float*  vsum = (float*)(smraw + VSUM_OFF);
    const uint32_t sbase = (uint32_t)__cvta_generic_to_shared(smraw);

    const int tid = threadIdx.x, warp = tid >> 5;
    const int vh = blockIdx.x, b = blockIdx.y;

    // segment max from the 8 tile maxima
    float bm8[8];
#pragma unroll
    for (int cb = 0; cb < 8; cb++) bm8[cb] = g_bmax[b * 8 + cb];
    float sgm = bm8[0];
#pragma unroll
    for (int cb = 1; cb < 8; cb++) sgm = fmaxf(sgm, bm8[cb]);

    if (tid < M) {
        float s = 0.f;
#pragma unroll
        for (int cb = 0; cb < 8; cb++)
            s += __expf(bm8[cb] - sgm) * g_esum[(b * 8 + cb) * M + tid];
        ksm[tid] = (s * (1.f / ESCALE) + NP * EPS_PHI) * (INV_SQRT_M * KSCALE);
    }
    if (tid < 128) vsum[tid] = 0.f;

    float corrf[8];
#pragma unroll
    for (int cb = 0; cb < 8; cb++)
        corrf[cb] = __expf(bm8[cb] - sgm) * (INV_SQRT_M * KSCALE / ESCALE);

    const __half* Ke = g_Ke + (size_t)b * NP * M;
    const float*  Vb = V    + (size_t)b * NP * DV + vh * 128;

    // ================= PHASE 1: KV-half into smem =================
    const int wr = warp & 7, wv = warp >> 3;

    auto copyA = [&](int s, int ch) {
        uint32_t abase = sbase + ST_OFF + s * ST_SZ;
        const __half* src = Ke + (size_t)(ch * 64) * M;
#pragma unroll
        for (int u = 0; u < 4; u++) {
            int i = tid + u * 512, t = i >> 5, q = i & 31;
            cp16(abase + (t * LDA + q * 8) * 2, src + (size_t)t * M + q * 8);
        }
        asm volatile("cp.async.commit_group;");
    };

    float4 Breg[4], Breg2[4];
    auto loadB = [&](float4* rg, int ch) {
        const float* src = Vb + (size_t)(ch * 64) * DV;
#pragma unroll
        for (int u = 0; u < 4; u++) {
            int i = tid + u * 512, t = i >> 5, q = i & 31;
            rg[u] = ((const float4*)(src + (size_t)t * DV))[q];
        }
    };
    float4 vpart = make_float4(0.f, 0.f, 0.f, 0.f);
    auto storeB = [&](const float4* rg, int s, float cf) {
        __half* Bs = (__half*)(smraw + ST_OFF + s * ST_SZ + 33792);
#pragma unroll
        for (int u = 0; u < 4; u++) {
            int i = tid + u * 512, t = i >> 5, q = i & 31;
            float4 f = rg[u];
            vpart.x += f.x; vpart.y += f.y; vpart.z += f.z; vpart.w += f.w;
            uint2 w = make_uint2(h2bits(__floats2half2_rn(f.x * cf, f.y * cf)),
                                 h2bits(__floats2half2_rn(f.z * cf, f.w * cf)));
            *(uint2*)(Bs + t * LDB + q * 4) = w;
        }
    };

    wmma::fragment<wmma::accumulator, 16, 16, 16, float> c1[2][4];
#pragma unroll
    for (int i = 0; i < 2; i++)
#pragma unroll
        for (int j = 0; j < 4; j++) wmma::fill_fragment(c1[i][j], 0.f);

    copyA(0, 0);
    loadB(Breg, 0);

    for (int ch = 0; ch < 8; ch++) {
        int s = ch & 1;
        if (ch < 7) copyA(s ^ 1, ch + 1);
        if (ch < 7) asm volatile("cp.async.wait_group 1;");
        else        asm volatile("cp.async.wait_group 0;");
        storeB(Breg, s, corrf[ch]);
        __syncthreads();
        if (ch < 7) loadB(Breg2, ch + 1);

        const __half* As = (const __half*)(smraw + ST_OFF + s * ST_SZ);
        const __half* Bs = As + 33792 / 2;
#pragma unroll
        for (int kk = 0; kk < 64; kk += 16) {
            wmma::fragment<wmma::matrix_a, 16, 16, 16, __half, wmma::col_major> a[2];
#pragma unroll
            for (int i = 0; i < 2; i++)
                wmma::load_matrix_sync(a[i], As + kk * LDA + wr * 32 + i * 16, LDA);
#pragma unroll
            for (int j = 0; j < 4; j++) {
                wmma::fragment<wmma::matrix_b, 16, 16, 16, __half, wmma::row_major> bf;
                wmma::load_matrix_sync(bf, Bs + kk * LDB + wv * 64 + j * 16, LDB);
#pragma unroll
                for (int i = 0; i < 2; i++)
                    wmma::mma_sync(c1[i][j], a[i], bf, c1[i][j]);
            }
        }
        __syncthreads();
#pragma unroll
        for (int u = 0; u < 4; u++) Breg[u] = Breg2[u];
    }

    // phase-2 chunk-0 A prefetch (ST region now free)
    {
        uint32_t abase = sbase + AS2_OFF;
        const __half* src = g_Qh + (size_t)b * NP * M;
#pragma unroll
        for (int u = 0; u < 4; u++) {
            int i = tid + u * 512, t = i >> 5, q = i & 31;
            cp16(abase + (t * LDA + q * 8) * 2, src + (size_t)t * M + q * 8);
        }
        asm volatile("cp.async.commit_group;");
    }

    {
        int q = tid & 31;
        atomicAdd(&vsum[q * 4 + 0], vpart.x);
        atomicAdd(&vsum[q * 4 + 1], vpart.y);
        atomicAdd(&vsum[q * 4 + 2], vpart.z);
        atomicAdd(&vsum[q * 4 + 3], vpart.w);
    }
#pragma unroll
    for (int i = 0; i < 2; i++)
#pragma unroll
        for (int j = 0; j < 4; j++) {
            wmma::fragment<wmma::accumulator, 16, 16, 16, __half> hf;
#pragma unroll
            for (int e = 0; e < hf.num_elements; e++)
                hf.x[e] = __float2half_rn(c1[i][j].x[e]);
            wmma::store_matrix_sync(KVs + (wr * 32 + i * 16) * LDB + wv * 64 + j * 16,
                                    hf, LDB, wmma::mem_row_major);
        }

    // ================= PHASE 2: 8 pipelined 64-token chunks =================
    const int kh  = warp >> 3;
    const int pos = warp & 7;
    const int tr  = pos >> 2;
    const int vc  = pos & 3;
    const __half* Qh = g_Qh + (size_t)b * NP * M;
    float* CsK = (float*)(smraw + CS_OFF + kh * CS_SZ);
    const float* Cs0 = (const float*)(smraw + CS_OFF);
    const float* Cs1 = (const float*)(smraw + CS_OFF + CS_SZ);

    for (int c = 0; c < 8; c++) {
        int s = c & 1;
        asm volatile("cp.async.wait_group 0;");
        __syncthreads();

        if (c < 7) {
            uint32_t abase = sbase + AS2_OFF + (s ^ 1) * AS2_SZ;
            const __half* src = Qh + (size_t)((c + 1) * 64) * M;
#pragma unroll
            for (int u = 0; u < 4; u++) {
                int i = tid + u * 512, t = i >> 5, q = i & 31;
                cp16(abase + (t * LDA + q * 8) * 2, src + (size_t)t * M + q * 8);
            }
            asm volatile("cp.async.commit_group;");
        }

        const __half* As2 = (const __half*)(smraw + AS2_OFF + s * AS2_SZ);
        {
            int row = tid >> 3, q8 = tid & 7;
            const __half2* qrow = (const __half2*)(As2 + row * LDA + q8 * 32);
            const float* kk2 = ksm + q8 * 32;
            float np = 0.f, qs = 0.f;
#pragma unroll
            for (int mm = 0; mm < 16; mm++) {
                float2 q2 = __half22float2(qrow[mm]);
                np += q2.x * kk2[mm * 2] + q2.y * kk2[mm * 2 + 1];
                qs += q2.x + q2.y;
            }
#pragma unroll
            for (int o = 4; o > 0; o >>= 1) {
                np += __shfl_xor_sync(0xffffffffu, np, o);
                qs += __shfl_xor_sync(0xffffffffu, qs, o);
            }
            if (q8 == 0) { normbuf[row] = np; qsumbuf[row] = qs; }
        }

        wmma::fragment<wmma::accumulator, 16, 16, 16, float> c2[2][2];
#pragma unroll
        for (int i = 0; i < 2; i++)
#pragma unroll
            for (int j = 0; j < 2; j++) wmma::fill_fragment(c2[i][j], 0.f);

#pragma unroll
        for (int ks = 0; ks < 8; ks++) {
            int kk = kh * 128 + ks * 16;
            wmma::fragment<wmma::matrix_a, 16, 16, 16, __half, wmma::row_major> a[2];
            wmma::fragment<wmma::matrix_b, 16, 16, 16, __half, wmma::row_major> bf[2];
#pragma unroll
            for (int i = 0; i < 2; i++)
                wmma::load_matrix_sync(a[i], As2 + (tr * 32 + i * 16) * LDA + kk, LDA);
#pragma unroll
            for (int j = 0; j < 2; j++)
                wmma::load_matrix_sync(bf[j], KVs + kk * LDB + vc * 32 + j * 16, LDB);
#pragma unroll
            for (int i = 0; i < 2; i++)
#pragma unroll
                for (int j = 0; j < 2; j++)
                    wmma::mma_sync(c2[i][j], a[i], bf[j], c2[i][j]);
        }
#pragma unroll
        for (int i = 0; i < 2; i++)
#pragma unroll
            for (int j = 0; j < 2; j++)
                wmma::store_matrix_sync(CsK + (tr * 32 + i * 16) * LDC + vc * 32 + j * 16,
                                        c2[i][j], LDC, wmma::mem_row_major);
        __syncthreads();

        float* op = out + ((size_t)(b * NP + c * 64)) * DV + vh * 128;
#pragma unroll
        for (int it = 0; it < 4; it++) {
            int i = it * 512 + tid;                // 2048 float4
            int r = i >> 5, c4 = (i & 31) * 4;
            float inv = 1.0f / (normbuf[r] + NORM_EPS);
            float q1 = qsumbuf[r] * C2F;
            const float* p0 = Cs0 + r * LDC + c4;
            const float* p1 = Cs1 + r * LDC + c4;
            float4 o;
            o.x = (p0[0] + p1[0] + q1 * vsum[c4 + 0]) * inv;
            o.y = (p0[1] + p1[1] + q1 * vsum[c4 + 1]) * inv;
            o.z = (p0[2] + p1[2] + q1 * vsum[c4 + 2]) * inv;
            o.w = (p0[3] + p1[3] + q1 * vsum[c4 + 3]) * inv;
            *(float4*)(op + (size_t)r * DV + c4) = o;
        }
    }
}

// ---------------- launch ------------------------------------------------------
extern "C" void kernel_launch(void* const* d_in, const int* in_sizes, int n_in,
                              void* d_out, int out_size) {
    const float* Q     = (const float*)d_in[0];
    const float* K     = (const float*)d_in[1];
    const float* V     = (const float*)d_in[2];
    const float* omega = (const float*)d_in[3];
    float* out = (float*)d_out;

    cudaFuncSetAttribute(phi_wmma_kernel, cudaFuncAttributeMaxDynamicSharedMemorySize, PHI_SMEM);
    cudaFuncSetAttribute(fused_kernel,    cudaFuncAttributeMaxDynamicSharedMemorySize, SMEMF);

    phi_wmma_kernel<<<2 * NTILES, 256, PHI_SMEM>>>(Q, K, omega);
    fused_kernel<<<dim3(2, NB), 512, SMEMF>>>(V, out);
}

// round 12
// speedup vs baseline: 1.3590x; 1.0992x over previous
#include <cuda_runtime.h>
#include <cuda_fp16.h>
#include <mma.h>
#include <math.h>
#include <stdint.h>

using namespace nvcuda;

#define N_TOK 32768
#define NB 64
#define NP 512
#define D 128
#define M 256
#define DV 256
#define EPS_PHI 1e-4f
#define EPS_NORM 1e-8f
#define INV_SQRT_M 0.0625f
#define XSCALE 0.29730177875068026f   // 1/128^0.25
#define KSCALE 256.0f
#define QSCALE 256.0f
#define ESCALE 512.0f
#define C2F (EPS_PHI * INV_SQRT_M * KSCALE)
#define NORM_EPS (EPS_NORM * KSCALE * QSCALE)

#define NTILE 64
#define NTILES (N_TOK / NTILE)

// ---------------- scratch ------------------------------------------------------
__device__ float  g_bmax[NTILES];
__device__ float  g_esum[NTILES * M];
__device__ __align__(16) __half g_Qh[N_TOK * M];
__device__ __align__(16) __half g_Ke[N_TOK * M];

__device__ __forceinline__ void cp16(uint32_t dst, const void* src) {
    asm volatile("cp.async.cg.shared.global [%0], [%1], 16;" :: "r"(dst), "l"(src));
}
__device__ __forceinline__ uint32_t h2bits(__half2 h) { return *(uint32_t*)&h; }

// ---------------- phi: U = X@omega (fp16 MMA, fp32 accum) — unchanged R11 ----
#define PHI_LDA 136
#define PHI_LDB 264
#define PHI_LDC 260
#define PHI_SMEM 87552

__global__ __launch_bounds__(256, 2) void phi_wmma_kernel(
    const float* __restrict__ Q, const float* __restrict__ K,
    const float* __restrict__ omega) {
    extern __shared__ char smraw[];
    __half* Ahi = (__half*)smraw;
    __half* Bhi = (__half*)(smraw + 17408);
    float*  Cs  = (float*)smraw;
    float*  hsm = (float*)(smraw + 84992);
    float*  mxs = (float*)(smraw + 85248);
    float2* esb = (float2*)(smraw + 85504);

    const int tid  = threadIdx.x;
    const int warp = tid >> 5, lane = tid & 31;
    const bool isq = blockIdx.x < NTILES;
    const int tile = isq ? blockIdx.x : blockIdx.x - NTILES;
    const int row0 = tile * NTILE;
    const float* X = isq ? Q : K;

    {
        int r = tid >> 2, j = tid & 3;
        const float4* src = (const float4*)(X + (size_t)(row0 + r) * D + j * 32);
        __half* ah = Ahi + r * PHI_LDA + j * 32;
        float ss = 0.f;
#pragma unroll
        for (int q = 0; q < 8; q++) {
            float4 v = src[q];
            v.x *= XSCALE; v.y *= XSCALE; v.z *= XSCALE; v.w *= XSCALE;
            ss += v.x * v.x + v.y * v.y + v.z * v.z + v.w * v.w;
            uint2 w = make_uint2(h2bits(__floats2half2_rn(v.x, v.y)),
                                 h2bits(__floats2half2_rn(v.z, v.w)));
            *(uint2*)(ah + q * 4) = w;
        }
        ss += __shfl_xor_sync(0xffffffffu, ss, 1);
        ss += __shfl_xor_sync(0xffffffffu, ss, 2);
        if (j == 0) hsm[r] = 0.5f * ss;
    }
#pragma unroll
    for (int it = 0; it < 32; it++) {
        int i = it * 256 + tid;
        int rr = i >> 6, c4 = i & 63;
        float4 v = ((const float4*)omega)[i];
        uint2 w = make_uint2(h2bits(__floats2half2_rn(v.x, v.y)),
                             h2bits(__floats2half2_rn(v.z, v.w)));
        *(uint2*)(Bhi + rr * PHI_LDB + c4 * 4) = w;
    }
    __syncthreads();

    const int wr = warp >> 2, wc = warp & 3;
    wmma::fragment<wmma::accumulator, 16, 16, 16, float> c[2][4];
#pragma unroll
    for (int i = 0; i < 2; i++)
#pragma unroll
        for (int j = 0; j < 4; j++) wmma::fill_fragment(c[i][j], 0.f);

#pragma unroll
    for (int ks = 0; ks < 8; ks++) {
        int kk = ks * 16;
        wmma::fragment<wmma::matrix_a, 16, 16, 16, __half, wmma::row_major> ah[2];
        wmma::fragment<wmma::matrix_b, 16, 16, 16, __half, wmma::row_major> bh[4];
#pragma unroll
        for (int i = 0; i < 2; i++)
            wmma::load_matrix_sync(ah[i], Ahi + (wr * 32 + i * 16) * PHI_LDA + kk, PHI_LDA);
#pragma unroll
        for (int j = 0; j < 4; j++)
            wmma::load_matrix_sync(bh[j], Bhi + kk * PHI_LDB + wc * 64 + j * 16, PHI_LDB);
#pragma unroll
        for (int i = 0; i < 2; i++)
#pragma unroll
            for (int j = 0; j < 4; j++)
                wmma::mma_sync(c[i][j], ah[i], bh[j], c[i][j]);
    }
    __syncthreads();

    if (isq) {
#pragma unroll
        for (int i = 0; i < 2; i++)
#pragma unroll
            for (int j = 0; j < 4; j++)
                wmma::store_matrix_sync(Cs + (wr * 32 + i * 16) * PHI_LDC + wc * 64 + j * 16,
                                        c[i][j], PHI_LDC, wmma::mem_row_major);
        __syncthreads();
#pragma unroll
        for (int rr = 0; rr < 8; rr++) {
            int row = warp * 8 + rr;
            float mx = -INFINITY;
#pragma unroll
            for (int cc = lane; cc < M; cc += 32) mx = fmaxf(mx, Cs[row * PHI_LDC + cc]);
#pragma unroll
            for (int o = 16; o > 0; o >>= 1) mx = fmaxf(mx, __shfl_xor_sync(0xffffffffu, mx, o));
            if (lane == 0) mxs[row] = mx;
        }
        __syncthreads();
#pragma unroll
        for (int it = 0; it < 32; it++) {
            int i = it * 256 + tid;
            int row = i >> 7, c2 = i & 127;
            float hm = hsm[row] + mxs[row];
            float2 u = *(const float2*)&Cs[row * PHI_LDC + c2 * 2];
            float a = (__expf(u.x - hm) + EPS_PHI) * (INV_SQRT_M * QSCALE);
            float b = (__expf(u.y - hm) + EPS_PHI) * (INV_SQRT_M * QSCALE);
            ((__half2*)g_Qh)[(size_t)(row0 + row) * (M / 2) + c2] = __floats2half2_rn(a, b);
        }
    } else {
        float bm = -INFINITY;
#pragma unroll
        for (int i = 0; i < 2; i++)
#pragma unroll
            for (int j = 0; j < 4; j++)
#pragma unroll
                for (int e = 0; e < c[i][j].num_elements; e++)
                    bm = fmaxf(bm, c[i][j].x[e]);
#pragma unroll
        for (int o = 16; o > 0; o >>= 1) bm = fmaxf(bm, __shfl_xor_sync(0xffffffffu, bm, o));
        if (lane == 0) mxs[warp] = bm;
#pragma unroll
        for (int i = 0; i < 2; i++)
#pragma unroll
            for (int j = 0; j < 4; j++)
                wmma::store_matrix_sync(Cs + (wr * 32 + i * 16) * PHI_LDC + wc * 64 + j * 16,
                                        c[i][j], PHI_LDC, wmma::mem_row_major);
        __syncthreads();
        float bmax = mxs[0];
#pragma unroll
        for (int w = 1; w < 8; w++) bmax = fmaxf(bmax, mxs[w]);

        float2 es = make_float2(0.f, 0.f);
#pragma unroll
        for (int it = 0; it < 32; it++) {
            int i = it * 256 + tid;
            int row = i >> 7, c2 = i & 127;
            float hm = hsm[row] + bmax;
            float2 u = *(const float2*)&Cs[row * PHI_LDC + c2 * 2];
            float a = __expf(u.x - hm) * ESCALE;
            float b = __expf(u.y - hm) * ESCALE;
            es.x += a; es.y += b;
            ((__half2*)g_Ke)[(size_t)(row0 + row) * (M / 2) + c2] = __floats2half2_rn(a, b);
        }
        esb[tid] = es;
        __syncthreads();
        if (tid < 128) {
            float2 t0 = esb[tid], t1 = esb[tid + 128];
            g_esum[tile * M + tid * 2]     = t0.x + t1.x;
            g_esum[tile * M + tid * 2 + 1] = t0.y + t1.y;
        }
        if (tid == 0) g_bmax[tile] = bmax;
    }
}

// ---------------- fused segment kernel ---------------------------------------
// KVs: [272][136] halves (rows 0-255 KV, 256 vsum, 257-271 zero) = 73984
#define LDA 264          // phase-1 Ke tile stride
#define LDB 136
#define LDA2 280         // phase-2 As2 stride (272 cols + pad)
#define ST_OFF  74752    // phase-1: 2 x (A 33792 + B 17408)
#define ST_SZ   51200
#define AS2_OFF 74752    // phase-2: 2 x [128][280] halves
#define AS2_SZ  71680
#define KSM_OFF 218112
#define VSUM_OFF 219136
#define SMEMF   220160

__global__ __launch_bounds__(512, 1) void fused_kernel(const float* __restrict__ V,
                                                       float* __restrict__ out) {
    extern __shared__ char smraw[];
    __half* KVs  = (__half*)smraw;
    float*  ksm  = (float*)(smraw + KSM_OFF);
    float*  vsum = (float*)(smraw + VSUM_OFF);
    const uint32_t sbase = (uint32_t)__cvta_generic_to_shared(smraw);

    const int tid = threadIdx.x, warp = tid >> 5;
    const int vh = blockIdx.x, b = blockIdx.y;

    float bm8[8];
#pragma unroll
    for (int cb = 0; cb < 8; cb++) bm8[cb] = g_bmax[b * 8 + cb];
    float sgm = bm8[0];
#pragma unroll
    for (int cb = 1; cb < 8; cb++) sgm = fmaxf(sgm, bm8[cb]);

    if (tid < M) {
        float s = 0.f;
#pragma unroll
        for (int cb = 0; cb < 8; cb++)
            s += __expf(bm8[cb] - sgm) * g_esum[(b * 8 + cb) * M + tid];
        ksm[tid] = (s * (1.f / ESCALE) + NP * EPS_PHI) * (INV_SQRT_M * KSCALE);
    }
    if (tid < 128) vsum[tid] = 0.f;
    // zero KVs aug rows 257-271 (15*136 halves = 1020 uints)
    for (int i = tid; i < 1020; i += 512)
        ((uint32_t*)KVs)[(257 * 136) / 2 + i] = 0u;

    float corrf[8];
#pragma unroll
    for (int cb = 0; cb < 8; cb++)
        corrf[cb] = __expf(bm8[cb] - sgm) * (INV_SQRT_M * KSCALE / ESCALE);

    const __half* Ke = g_Ke + (size_t)b * NP * M;
    const float*  Vb = V    + (size_t)b * NP * DV + vh * 128;

    // ================= PHASE 1: KV-half into KVs =================
    const int wr = warp & 7, wv = warp >> 3;

    auto copyA = [&](int s, int ch) {
        uint32_t abase = sbase + ST_OFF + s * ST_SZ;
        const __half* src = Ke + (size_t)(ch * 64) * M;
#pragma unroll
        for (int u = 0; u < 4; u++) {
            int i = tid + u * 512, t = i >> 5, q = i & 31;
            cp16(abase + (t * LDA + q * 8) * 2, src + (size_t)t * M + q * 8);
        }
        asm volatile("cp.async.commit_group;");
    };

    float4 Breg[4], Breg2[4];
    auto loadB = [&](float4* rg, int ch) {
        const float* src = Vb + (size_t)(ch * 64) * DV;
#pragma unroll
        for (int u = 0; u < 4; u++) {
            int i = tid + u * 512, t = i >> 5, q = i & 31;
            rg[u] = ((const float4*)(src + (size_t)t * DV))[q];
        }
    };
    float4 vpart = make_float4(0.f, 0.f, 0.f, 0.f);
    auto storeB = [&](const float4* rg, int s, float cf) {
        __half* Bs = (__half*)(smraw + ST_OFF + s * ST_SZ + 33792);
#pragma unroll
        for (int u = 0; u < 4; u++) {
            int i = tid + u * 512, t = i >> 5, q = i & 31;
            float4 f = rg[u];
            vpart.x += f.x; vpart.y += f.y; vpart.z += f.z; vpart.w += f.w;
            uint2 w = make_uint2(h2bits(__floats2half2_rn(f.x * cf, f.y * cf)),
                                 h2bits(__floats2half2_rn(f.z * cf, f.w * cf)));
            *(uint2*)(Bs + t * LDB + q * 4) = w;
        }
    };

    wmma::fragment<wmma::accumulator, 16, 16, 16, float> c1[2][4];
#pragma unroll
    for (int i = 0; i < 2; i++)
#pragma unroll
        for (int j = 0; j < 4; j++) wmma::fill_fragment(c1[i][j], 0.f);

    copyA(0, 0);
    loadB(Breg, 0);

    for (int ch = 0; ch < 8; ch++) {
        int s = ch & 1;
        if (ch < 7) copyA(s ^ 1, ch + 1);
        if (ch < 7) asm volatile("cp.async.wait_group 1;");
        else        asm volatile("cp.async.wait_group 0;");
        storeB(Breg, s, corrf[ch]);
        __syncthreads();
        if (ch < 7) loadB(Breg2, ch + 1);

        const __half* As = (const __half*)(smraw + ST_OFF + s * ST_SZ);
        const __half* Bs = As + 33792 / 2;
#pragma unroll
        for (int kk = 0; kk < 64; kk += 16) {
            wmma::fragment<wmma::matrix_a, 16, 16, 16, __half, wmma::col_major> a[2];
#pragma unroll
            for (int i = 0; i < 2; i++)
                wmma::load_matrix_sync(a[i], As + kk * LDA + wr * 32 + i * 16, LDA);
#pragma unroll
            for (int j = 0; j < 4; j++) {
                wmma::fragment<wmma::matrix_b, 16, 16, 16, __half, wmma::row_major> bf;
                wmma::load_matrix_sync(bf, Bs + kk * LDB + wv * 64 + j * 16, LDB);
#pragma unroll
                for (int i = 0; i < 2; i++)
                    wmma::mma_sync(c1[i][j], a[i], bf, c1[i][j]);
            }
        }
        __syncthreads();
#pragma unroll
        for (int u = 0; u < 4; u++) Breg[u] = Breg2[u];
    }

    // phase-2 chunk-0 A prefetch (128 tokens x 256 m)
    {
        uint32_t abase = sbase + AS2_OFF;
        const __half* src = g_Qh + (size_t)b * NP * M;
#pragma unroll
        for (int u = 0; u < 8; u++) {
            int i = tid + u * 512, t = i >> 5, q = i & 31;
            cp16(abase + (t * LDA2 + q * 8) * 2, src + (size_t)t * M + q * 8);
        }
        asm volatile("cp.async.commit_group;");
    }

    {
        int q = tid & 31;
        atomicAdd(&vsum[q * 4 + 0], vpart.x);
        atomicAdd(&vsum[q * 4 + 1], vpart.y);
        atomicAdd(&vsum[q * 4 + 2], vpart.z);
        atomicAdd(&vsum[q * 4 + 3], vpart.w);
    }
#pragma unroll
    for (int i = 0; i < 2; i++)
#pragma unroll
        for (int j = 0; j < 4; j++) {
            wmma::fragment<wmma::accumulator, 16, 16, 16, __half> hf;
#pragma unroll
            for (int e = 0; e < hf.num_elements; e++)
                hf.x[e] = __float2half_rn(c1[i][j].x[e]);
            wmma::store_matrix_sync(KVs + (wr * 32 + i * 16) * LDB + wv * 64 + j * 16,
                                    hf, LDB, wmma::mem_row_major);
        }
    __syncthreads();
    // write aug row 256 = vsum (vsum finalized by the barrier above)
    if (tid < 128) KVs[256 * 136 + tid] = __float2half_rn(vsum[tid]);

    // ================= PHASE 2: 4 chunks of 128 tokens =================
    const int tr = warp >> 2, vc = warp & 3;    // 4x4 positions, 32x32 tiles
    const __half* Qh = g_Qh + (size_t)b * NP * M;

    for (int c = 0; c < 4; c++) {
        int s = c & 1;
        asm volatile("cp.async.wait_group 0;");
        __syncthreads();   // As2 stage s ready; KVs row-256 visible (c==0)

        if (c < 3) {
            uint32_t abase = sbase + AS2_OFF + (s ^ 1) * AS2_SZ;
            const __half* src = Qh + (size_t)((c + 1) * 128) * M;
#pragma unroll
            for (int u = 0; u < 8; u++) {
                int i = tid + u * 512, t = i >> 5, q = i & 31;
                cp16(abase + (t * LDA2 + q * 8) * 2, src + (size_t)t * M + q * 8);
            }
            asm volatile("cp.async.commit_group;");
        }

        __half* As2 = (__half*)(smraw + AS2_OFF + s * AS2_SZ);
        {   // norm + prescale: 4 threads/row, 128 rows
            int row = tid >> 2, j4 = tid & 3;
            __half2* arow = (__half2*)(As2 + row * LDA2 + j4 * 64);
            const float* kk2 = ksm + j4 * 64;
            float np = 0.f, qs = 0.f;
#pragma unroll
            for (int mm = 0; mm < 32; mm++) {
                float2 q2 = __half22float2(arow[mm]);
                np += q2.x * kk2[mm * 2] + q2.y * kk2[mm * 2 + 1];
                qs += q2.x + q2.y;
            }
            np += __shfl_xor_sync(0xffffffffu, np, 1);
            np += __shfl_xor_sync(0xffffffffu, np, 2);
            qs += __shfl_xor_sync(0xffffffffu, qs, 1);
            qs += __shfl_xor_sync(0xffffffffu, qs, 2);
            float inv = 1.0f / (np + NORM_EPS);
#pragma unroll
            for (int mm = 0; mm < 32; mm++) {
                float2 q2 = __half22float2(arow[mm]);
                arow[mm] = __floats2half2_rn(q2.x * inv, q2.y * inv);
            }
            if (j4 == 0) {   // aug cols 256-271: (q1, 0, 0, ...)
                __half2* aug = (__half2*)(As2 + row * LDA2 + 256);
                aug[0] = __floats2half2_rn(qs * C2F * inv, 0.f);
#pragma unroll
                for (int z = 1; z < 8; z++) aug[z] = __floats2half2_rn(0.f, 0.f);
            }
        }
        __syncthreads();

        wmma::fragment<wmma::accumulator, 16, 16, 16, float> c2[2][2];
#pragma unroll
        for (int i = 0; i < 2; i++)
#pragma unroll
            for (int j = 0; j < 2; j++) wmma::fill_fragment(c2[i][j], 0.f);

#pragma unroll
        for (int ks = 0; ks < 17; ks++) {
            int kk = ks * 16;
            wmma::fragment<wmma::matrix_a, 16, 16, 16, __half, wmma::row_major> a[2];
            wmma::fragment<wmma::matrix_b, 16, 16, 16, __half, wmma::row_major> bf[2];
#pragma unroll
            for (int i = 0; i < 2; i++)
                wmma::load_matrix_sync(a[i], As2 + (tr * 32 + i * 16) * LDA2 + kk, LDA2);
#pragma unroll
            for (int j = 0; j < 2; j++)
                wmma::load_matrix_sync(bf[j], KVs + kk * LDB + vc * 32 + j * 16, LDB);
#pragma unroll
            for (int i = 0; i < 2; i++)
#pragma unroll
                for (int j = 0; j < 2; j++)
                    wmma::mma_sync(c2[i][j], a[i], bf[j], c2[i][j]);
        }

        // direct global store (rows already normalized)
        float* op = out + ((size_t)(b * NP + c * 128 + tr * 32)) * DV + vh * 128 + vc * 32;
#pragma unroll
        for (int i = 0; i < 2; i++)
#pragma unroll
            for (int j = 0; j < 2; j++)
                wmma::store_matrix_sync(op + (size_t)(i * 16) * DV + j * 16,
                                        c2[i][j], DV, wmma::mem_row_major);
    }
}

// ---------------- launch ------------------------------------------------------
extern "C" void kernel_launch(void* const* d_in, const int* in_sizes, int n_in,
                              void* d_out, int out_size) {
    const float* Q     = (const float*)d_in[0];
    const float* K     = (const float*)d_in[1];
    const float* V     = (const float*)d_in[2];
    const float* omega = (const float*)d_in[3];
    float* out = (float*)d_out;

    cudaFuncSetAttribute(phi_wmma_kernel, cudaFuncAttributeMaxDynamicSharedMemorySize, PHI_SMEM);
    cudaFuncSetAttribute(fused_kernel,    cudaFuncAttributeMaxDynamicSharedMemorySize, SMEMF);

    phi_wmma_kernel<<<2 * NTILES, 256, PHI_SMEM>>>(Q, K, omega);
    fused_kernel<<<dim3(2, NB), 512, SMEMF>>>(V, out);
}

// round 13
// speedup vs baseline: 1.4520x; 1.0684x over previous
#include <cuda_runtime.h>
#include <cuda_fp16.h>
#include <mma.h>
#include <math.h>
#include <stdint.h>

using namespace nvcuda;

#define N_TOK 32768
#define NB 64
#define NP 512
#define D 128
#define M 256
#define DV 256
#define EPS_PHI 1e-4f
#define EPS_NORM 1e-8f
#define INV_SQRT_M 0.0625f
#define XSCALE 0.29730177875068026f   // 1/128^0.25
#define KSCALE 256.0f
#define QSCALE 256.0f
#define ESCALE 512.0f
#define C2F (EPS_PHI * INV_SQRT_M * KSCALE)
#define NORM_EPS (EPS_NORM * KSCALE * QSCALE)

#define NTILE 64
#define NTILES (N_TOK / NTILE)

// ---------------- scratch ------------------------------------------------------
__device__ float  g_bmax[NTILES];
__device__ float  g_esum[NTILES * M];
__device__ __align__(16) __half g_Qh[N_TOK * M];
__device__ __align__(16) __half g_Ke[N_TOK * M];
__device__ __align__(16) __half g_Whi[D * M];

__device__ __forceinline__ void cp16(uint32_t dst, const void* src) {
    asm volatile("cp.async.cg.shared.global [%0], [%1], 16;" :: "r"(dst), "l"(src));
}
__device__ __forceinline__ uint32_t h2bits(__half2 h) { return *(uint32_t*)&h; }

__global__ void omega_split_kernel(const float* __restrict__ omega) {
    int i = blockIdx.x * 256 + threadIdx.x;
    g_Whi[i] = __float2half_rn(omega[i]);
}

// ---------------- phi: U = X@omega, frag-direct epilogue ---------------------
// 256 threads, 64 tokens/block, 2 blocks/SM.
// smem: Ahi [64][136] @0 (17408), Bhi [128][264] @17408 (67584)
//       hsm f32[64] @84992, mxs f32[64] @85248, mxs2 f32[64][4] @85504,
//       esum2 f32[2*256] @86528 -> 88576
#define PHI_LDA 136
#define PHI_LDB 264
#define PHI_SMEM 88576

__global__ __launch_bounds__(256, 2) void phi_wmma_kernel(
    const float* __restrict__ Q, const float* __restrict__ K) {
    extern __shared__ char smraw[];
    __half* Ahi = (__half*)smraw;
    __half* Bhi = (__half*)(smraw + 17408);
    float*  hsm = (float*)(smraw + 84992);
    float*  mxs = (float*)(smraw + 85248);
    float*  mxs2 = (float*)(smraw + 85504);
    float*  esum2 = (float*)(smraw + 86528);
    const uint32_t sbase = (uint32_t)__cvta_generic_to_shared(smraw);

    const int tid  = threadIdx.x;
    const int warp = tid >> 5, lane = tid & 31;
    const int r4 = lane >> 2, q4 = lane & 3;
    const bool isq = blockIdx.x < NTILES;
    const int tile = isq ? blockIdx.x : blockIdx.x - NTILES;
    const int row0 = tile * NTILE;
    const float* X = isq ? Q : K;

    // ---- async copy pre-split omega -> Bhi (flies under the X load) ----
#pragma unroll
    for (int u = 0; u < 16; u++) {
        int i = u * 256 + tid;              // 4096 16B chunks
        int r = i >> 5, q = i & 31;
        cp16(sbase + 17408 + r * (PHI_LDB * 2) + q * 16, g_Whi + r * 256 + q * 8);
    }
    asm volatile("cp.async.commit_group;");

    // ---- load X (scaled) -> Ahi, h per row ----
    {
        int r = tid >> 2, j = tid & 3;
        const float4* src = (const float4*)(X + (size_t)(row0 + r) * D + j * 32);
        __half* ah = Ahi + r * PHI_LDA + j * 32;
        float ss = 0.f;
#pragma unroll
        for (int q = 0; q < 8; q++) {
            float4 v = src[q];
            v.x *= XSCALE; v.y *= XSCALE; v.z *= XSCALE; v.w *= XSCALE;
            ss += v.x * v.x + v.y * v.y + v.z * v.z + v.w * v.w;
            uint2 w = make_uint2(h2bits(__floats2half2_rn(v.x, v.y)),
                                 h2bits(__floats2half2_rn(v.z, v.w)));
            *(uint2*)(ah + q * 4) = w;
        }
        ss += __shfl_xor_sync(0xffffffffu, ss, 1);
        ss += __shfl_xor_sync(0xffffffffu, ss, 2);
        if (j == 0) hsm[r] = 0.5f * ss;
    }
    asm volatile("cp.async.wait_group 0;");
    __syncthreads();

    // ---- MMA: warp tile 32 tokens x 64 features ----
    const int wr = warp >> 2, wc = warp & 3;
    wmma::fragment<wmma::accumulator, 16, 16, 16, float> c[2][4];
#pragma unroll
    for (int i = 0; i < 2; i++)
#pragma unroll
        for (int j = 0; j < 4; j++) wmma::fill_fragment(c[i][j], 0.f);

#pragma unroll
    for (int ks = 0; ks < 8; ks++) {
        int kk = ks * 16;
        wmma::fragment<wmma::matrix_a, 16, 16, 16, __half, wmma::row_major> ah[2];
        wmma::fragment<wmma::matrix_b, 16, 16, 16, __half, wmma::row_major> bh[4];
#pragma unroll
        for (int i = 0; i < 2; i++)
            wmma::load_matrix_sync(ah[i], Ahi + (wr * 32 + i * 16) * PHI_LDA + kk, PHI_LDA);
#pragma unroll
        for (int j = 0; j < 4; j++)
            wmma::load_matrix_sync(bh[j], Bhi + kk * PHI_LDB + wc * 64 + j * 16, PHI_LDB);
#pragma unroll
        for (int i = 0; i < 2; i++)
#pragma unroll
            for (int j = 0; j < 4; j++)
                wmma::mma_sync(c[i][j], ah[i], bh[j], c[i][j]);
    }
    // HMMA fp32 accum layout: elem k of lane l -> row (l>>2)+8*((k>>1)&1),
    //                         col (l&3)*2+(k&1)+8*((k>>2)&1)

    if (isq) {
        // per-row maxima from fragments
#pragma unroll
        for (int i = 0; i < 2; i++) {
            float mA = -INFINITY, mB = -INFINITY;
#pragma unroll
            for (int j = 0; j < 4; j++) {
                mA = fmaxf(mA, fmaxf(fmaxf(c[i][j].x[0], c[i][j].x[1]),
                                     fmaxf(c[i][j].x[4], c[i][j].x[5])));
                mB = fmaxf(mB, fmaxf(fmaxf(c[i][j].x[2], c[i][j].x[3]),
                                     fmaxf(c[i][j].x[6], c[i][j].x[7])));
            }
            mA = fmaxf(mA, __shfl_xor_sync(0xffffffffu, mA, 1));
            mA = fmaxf(mA, __shfl_xor_sync(0xffffffffu, mA, 2));
            mB = fmaxf(mB, __shfl_xor_sync(0xffffffffu, mB, 1));
            mB = fmaxf(mB, __shfl_xor_sync(0xffffffffu, mB, 2));
            if (q4 == 0) {
                mxs2[(wr * 32 + i * 16 + r4) * 4 + wc]     = mA;
                mxs2[(wr * 32 + i * 16 + r4 + 8) * 4 + wc] = mB;
            }
        }
        __syncthreads();
        if (tid < 64)
            mxs[tid] = fmaxf(fmaxf(mxs2[tid * 4], mxs2[tid * 4 + 1]),
                             fmaxf(mxs2[tid * 4 + 2], mxs2[tid * 4 + 3]));
        __syncthreads();
        // exp + direct gmem store
#pragma unroll
        for (int i = 0; i < 2; i++) {
            int rowA = wr * 32 + i * 16 + r4, rowB = rowA + 8;
            float hmA = hsm[rowA] + mxs[rowA];
            float hmB = hsm[rowB] + mxs[rowB];
            __half2* dA = (__half2*)(g_Qh + (size_t)(row0 + rowA) * M);
            __half2* dB = (__half2*)(g_Qh + (size_t)(row0 + rowB) * M);
#pragma unroll
            for (int j = 0; j < 4; j++) {
                int cb2 = (wc * 64 + j * 16) / 2 + q4;     // half2 index
#pragma unroll
                for (int hf = 0; hf < 2; hf++) {
                    int kb = hf * 4;
                    float a0 = (__expf(c[i][j].x[kb + 0] - hmA) + EPS_PHI) * (INV_SQRT_M * QSCALE);
                    float a1 = (__expf(c[i][j].x[kb + 1] - hmA) + EPS_PHI) * (INV_SQRT_M * QSCALE);
                    float b0 = (__expf(c[i][j].x[kb + 2] - hmB) + EPS_PHI) * (INV_SQRT_M * QSCALE);
                    float b1 = (__expf(c[i][j].x[kb + 3] - hmB) + EPS_PHI) * (INV_SQRT_M * QSCALE);
                    dA[cb2 + hf * 4] = __floats2half2_rn(a0, a1);
                    dB[cb2 + hf * 4] = __floats2half2_rn(b0, b1);
                }
            }
        }
    } else {
        // block max from fragments
        float bm = -INFINITY;
#pragma unroll
        for (int i = 0; i < 2; i++)
#pragma unroll
            for (int j = 0; j < 4; j++)
#pragma unroll
                for (int e = 0; e < 8; e++) bm = fmaxf(bm, c[i][j].x[e]);
#pragma unroll
        for (int o = 16; o > 0; o >>= 1) bm = fmaxf(bm, __shfl_xor_sync(0xffffffffu, bm, o));
        if (lane == 0) mxs[warp] = bm;
        __syncthreads();
        float bmax = mxs[0];
#pragma unroll
        for (int w = 1; w < 8; w++) bmax = fmaxf(bmax, mxs[w]);

        // exp + store + per-column partial sums (es[j*4 + hf*2 + parity])
        float es[16];
#pragma unroll
        for (int t = 0; t < 16; t++) es[t] = 0.f;
#pragma unroll
        for (int i = 0; i < 2; i++) {
            int rowA = wr * 32 + i * 16 + r4, rowB = rowA + 8;
            float hmA = hsm[rowA] + bmax;
            float hmB = hsm[rowB] + bmax;
            __half2* dA = (__half2*)(g_Ke + (size_t)(row0 + rowA) * M);
            __half2* dB = (__half2*)(g_Ke + (size_t)(row0 + rowB) * M);
#pragma unroll
            for (int j = 0; j < 4; j++) {
                int cb2 = (wc * 64 + j * 16) / 2 + q4;
#pragma unroll
                for (int hf = 0; hf < 2; hf++) {
                    int kb = hf * 4;
                    float a0 = __expf(c[i][j].x[kb + 0] - hmA) * ESCALE;
                    float a1 = __expf(c[i][j].x[kb + 1] - hmA) * ESCALE;
                    float b0 = __expf(c[i][j].x[kb + 2] - hmB) * ESCALE;
                    float b1 = __expf(c[i][j].x[kb + 3] - hmB) * ESCALE;
                    dA[cb2 + hf * 4] = __floats2half2_rn(a0, a1);
                    dB[cb2 + hf * 4] = __floats2half2_rn(b0, b1);
                    es[j * 4 + hf * 2 + 0] += a0 + b0;
                    es[j * 4 + hf * 2 + 1] += a1 + b1;
                }
            }
        }
        // reduce over the 8 lanes sharing q4 (rows within warp)
#pragma unroll
        for (int t = 0; t < 16; t++) {
            es[t] += __shfl_xor_sync(0xffffffffu, es[t], 4);
            es[t] += __shfl_xor_sync(0xffffffffu, es[t], 8);
            es[t] += __shfl_xor_sync(0xffffffffu, es[t], 16);
        }
        if (lane < 4) {
#pragma unroll
            for (int j = 0; j < 4; j++)
#pragma unroll
                for (int hf = 0; hf < 2; hf++)
#pragma unroll
                    for (int p = 0; p < 2; p++) {
                        int col = wc * 64 + j * 16 + lane * 2 + p + 8 * hf;
                        esum2[wr * 256 + col] = es[j * 4 + hf * 2 + p];
                    }
        }
        __syncthreads();
        g_esum[tile * M + tid] = esum2[tid] + esum2[256 + tid];
        if (tid == 0) g_bmax[tile] = bmax;
    }
}

// ---------------- fused segment kernel ---------------------------------------
// KVs: [272][136] halves (rows 0-255 KV, 256 vsum, 257-271 zero)
#define LDA 264
#define LDB 136
#define LDA2 280
#define ST_OFF  74752
#define ST_SZ   51200
#define AS2_OFF 74752
#define AS2_SZ  71680
#define KSM_OFF 218112
#define VSUM_OFF 219136
#define INV_OFF 219648
#define SMEMF   220160

__global__ __launch_bounds__(512, 1) void fused_kernel(const float* __restrict__ V,
                                                       float* __restrict__ out) {
    extern __shared__ char smraw[];
    __half* KVs  = (__half*)smraw;
    float*  ksm  = (float*)(smraw + KSM_OFF);
    float*  vsum = (float*)(smraw + VSUM_OFF);
    float*  invbuf = (float*)(smraw + INV_OFF);
    const uint32_t sbase = (uint32_t)__cvta_generic_to_shared(smraw);

    const int tid = threadIdx.x, warp = tid >> 5, lane = tid & 31;
    const int r4 = lane >> 2;
    const int vh = blockIdx.x, b = blockIdx.y;

    float bm8[8];
#pragma unroll
    for (int cb = 0; cb < 8; cb++) bm8[cb] = g_bmax[b * 8 + cb];
    float sgm = bm8[0];
#pragma unroll
    for (int cb = 1; cb < 8; cb++) sgm = fmaxf(sgm, bm8[cb]);

    if (tid < M) {
        float s = 0.f;
#pragma unroll
        for (int cb = 0; cb < 8; cb++)
            s += __expf(bm8[cb] - sgm) * g_esum[(b * 8 + cb) * M + tid];
        ksm[tid] = (s * (1.f / ESCALE) + NP * EPS_PHI) * (INV_SQRT_M * KSCALE);
    }
    if (tid < 128) vsum[tid] = 0.f;
    for (int i = tid; i < 1020; i += 512)
        ((uint32_t*)KVs)[(257 * 136) / 2 + i] = 0u;

    float corrf[8];
#pragma unroll
    for (int cb = 0; cb < 8; cb++)
        corrf[cb] = __expf(bm8[cb] - sgm) * (INV_SQRT_M * KSCALE / ESCALE);

    const __half* Ke = g_Ke + (size_t)b * NP * M;
    const float*  Vb = V    + (size_t)b * NP * DV + vh * 128;

    // ================= PHASE 1: KV-half into KVs =================
    const int wr = warp & 7, wv = warp >> 3;

    auto copyA = [&](int s, int ch) {
        uint32_t abase = sbase + ST_OFF + s * ST_SZ;
        const __half* src = Ke + (size_t)(ch * 64) * M;
#pragma unroll
        for (int u = 0; u < 4; u++) {
            int i = tid + u * 512, t = i >> 5, q = i & 31;
            cp16(abase + (t * LDA + q * 8) * 2, src + (size_t)t * M + q * 8);
        }
        asm volatile("cp.async.commit_group;");
    };

    float4 Breg[4], Breg2[4];
    auto loadB = [&](float4* rg, int ch) {
        const float* src = Vb + (size_t)(ch * 64) * DV;
#pragma unroll
        for (int u = 0; u < 4; u++) {
            int i = tid + u * 512, t = i >> 5, q = i & 31;
            rg[u] = ((const float4*)(src + (size_t)t * DV))[q];
        }
    };
    float4 vpart = make_float4(0.f, 0.f, 0.f, 0.f);
    auto storeB = [&](const float4* rg, int s, float cf) {
        __half* Bs = (__half*)(smraw + ST_OFF + s * ST_SZ + 33792);
#pragma unroll
        for (int u = 0; u < 4; u++) {
            int i = tid + u * 512, t = i >> 5, q = i & 31;
            float4 f = rg[u];
            vpart.x += f.x; vpart.y += f.y; vpart.z += f.z; vpart.w += f.w;
            uint2 w = make_uint2(h2bits(__floats2half2_rn(f.x * cf, f.y * cf)),
                                 h2bits(__floats2half2_rn(f.z * cf, f.w * cf)));
            *(uint2*)(Bs + t * LDB + q * 4) = w;
        }
    };

    wmma::fragment<wmma::accumulator, 16, 16, 16, float> c1[2][4];
#pragma unroll
    for (int i = 0; i < 2; i++)
#pragma unroll
        for (int j = 0; j < 4; j++) wmma::fill_fragment(c1[i][j], 0.f);

    copyA(0, 0);
    loadB(Breg, 0);

    for (int ch = 0; ch < 8; ch++) {
        int s = ch & 1;
        if (ch < 7) copyA(s ^ 1, ch + 1);
        if (ch < 7) asm volatile("cp.async.wait_group 1;");
        else        asm volatile("cp.async.wait_group 0;");
        storeB(Breg, s, corrf[ch]);
        __syncthreads();
        if (ch < 7) loadB(Breg2, ch + 1);

        const __half* As = (const __half*)(smraw + ST_OFF + s * ST_SZ);
        const __half* Bs = As + 33792 / 2;
#pragma unroll
        for (int kk = 0; kk < 64; kk += 16) {
            wmma::fragment<wmma::matrix_a, 16, 16, 16, __half, wmma::col_major> a[2];
#pragma unroll
            for (int i = 0; i < 2; i++)
                wmma::load_matrix_sync(a[i], As + kk * LDA + wr * 32 + i * 16, LDA);
#pragma unroll
            for (int j = 0; j < 4; j++) {
                wmma::fragment<wmma::matrix_b, 16, 16, 16, __half, wmma::row_major> bf;
                wmma::load_matrix_sync(bf, Bs + kk * LDB + wv * 64 + j * 16, LDB);
#pragma unroll
                for (int i = 0; i < 2; i++)
                    wmma::mma_sync(c1[i][j], a[i], bf, c1[i][j]);
            }
        }
        __syncthreads();
#pragma unroll
        for (int u = 0; u < 4; u++) Breg[u] = Breg2[u];
    }

    // phase-2 chunk-0 A prefetch
    {
        uint32_t abase = sbase + AS2_OFF;
        const __half* src = g_Qh + (size_t)b * NP * M;
#pragma unroll
        for (int u = 0; u < 8; u++) {
            int i = tid + u * 512, t = i >> 5, q = i & 31;
            cp16(abase + (t * LDA2 + q * 8) * 2, src + (size_t)t * M + q * 8);
        }
        asm volatile("cp.async.commit_group;");
    }

    {
        int q = tid & 31;
        atomicAdd(&vsum[q * 4 + 0], vpart.x);
        atomicAdd(&vsum[q * 4 + 1], vpart.y);
        atomicAdd(&vsum[q * 4 + 2], vpart.z);
        atomicAdd(&vsum[q * 4 + 3], vpart.w);
    }
#pragma unroll
    for (int i = 0; i < 2; i++)
#pragma unroll
        for (int j = 0; j < 4; j++) {
            wmma::fragment<wmma::accumulator, 16, 16, 16, __half> hf;
#pragma unroll
            for (int e = 0; e < hf.num_elements; e++)
                hf.x[e] = __float2half_rn(c1[i][j].x[e]);
            wmma::store_matrix_sync(KVs + (wr * 32 + i * 16) * LDB + wv * 64 + j * 16,
                                    hf, LDB, wmma::mem_row_major);
        }
    __syncthreads();
    if (tid < 128) KVs[256 * 136 + tid] = __float2half_rn(vsum[tid]);

    // ================= PHASE 2: 4 chunks of 128 tokens =================
    const int tr = warp >> 2, vc = warp & 3;
    const __half* Qh = g_Qh + (size_t)b * NP * M;

    for (int c = 0; c < 4; c++) {
        int s = c & 1;
        asm volatile("cp.async.wait_group 0;");
        __syncthreads();

        if (c < 3) {
            uint32_t abase = sbase + AS2_OFF + (s ^ 1) * AS2_SZ;
            const __half* src = Qh + (size_t)((c + 1) * 128) * M;
#pragma unroll
            for (int u = 0; u < 8; u++) {
                int i = tid + u * 512, t = i >> 5, q = i & 31;
                cp16(abase + (t * LDA2 + q * 8) * 2, src + (size_t)t * M + q * 8);
            }
            asm volatile("cp.async.commit_group;");
        }

        __half* As2 = (__half*)(smraw + AS2_OFF + s * AS2_SZ);
        {   // norm pass (read-only): np, qs -> invbuf, aug col
            int row = tid >> 2, j4 = tid & 3;
            const __half2* arow = (const __half2*)(As2 + row * LDA2 + j4 * 64);
            const float* kk2 = ksm + j4 * 64;
            float np = 0.f, qs = 0.f;
#pragma unroll
            for (int mm = 0; mm < 32; mm++) {
                float2 q2 = __half22float2(arow[mm]);
                np += q2.x * kk2[mm * 2] + q2.y * kk2[mm * 2 + 1];
                qs += q2.x + q2.y;
            }
            np += __shfl_xor_sync(0xffffffffu, np, 1);
            np += __shfl_xor_sync(0xffffffffu, np, 2);
            qs += __shfl_xor_sync(0xffffffffu, qs, 1);
            qs += __shfl_xor_sync(0xffffffffu, qs, 2);
            if (j4 == 0) {
                invbuf[row] = 1.0f / (np + NORM_EPS);
                __half2* aug = (__half2*)(As2 + row * LDA2 + 256);
                aug[0] = __floats2half2_rn(qs * C2F, 0.f);
#pragma unroll
                for (int z = 1; z < 8; z++) aug[z] = __floats2half2_rn(0.f, 0.f);
            }
        }
        __syncthreads();

        wmma::fragment<wmma::accumulator, 16, 16, 16, float> c2[2][2];
#pragma unroll
        for (int i = 0; i < 2; i++)
#pragma unroll
            for (int j = 0; j < 2; j++) wmma::fill_fragment(c2[i][j], 0.f);

#pragma unroll
        for (int ks = 0; ks < 17; ks++) {
            int kk = ks * 16;
            wmma::fragment<wmma::matrix_a, 16, 16, 16, __half, wmma::row_major> a[2];
            wmma::fragment<wmma::matrix_b, 16, 16, 16, __half, wmma::row_major> bf[2];
#pragma unroll
            for (int i = 0; i < 2; i++)
                wmma::load_matrix_sync(a[i], As2 + (tr * 32 + i * 16) * LDA2 + kk, LDA2);
#pragma unroll
            for (int j = 0; j < 2; j++)
                wmma::load_matrix_sync(bf[j], KVs + kk * LDB + vc * 32 + j * 16, LDB);
#pragma unroll
            for (int i = 0; i < 2; i++)
#pragma unroll
                for (int j = 0; j < 2; j++)
                    wmma::mma_sync(c2[i][j], a[i], bf[j], c2[i][j]);
        }

        // epilogue: per-row scaling via frag layout, direct gmem store
        float* op = out + ((size_t)(b * NP + c * 128 + tr * 32)) * DV + vh * 128 + vc * 32;
#pragma unroll
        for (int i = 0; i < 2; i++) {
            int rb = tr * 32 + i * 16;
            float invA = invbuf[rb + r4];
            float invB = invbuf[rb + r4 + 8];
#pragma unroll
            for (int j = 0; j < 2; j++) {
                c2[i][j].x[0] *= invA; c2[i][j].x[1] *= invA;
                c2[i][j].x[4] *= invA; c2[i][j].x[5] *= invA;
                c2[i][j].x[2] *= invB; c2[i][j].x[3] *= invB;
                c2[i][j].x[6] *= invB; c2[i][j].x[7] *= invB;
                wmma::store_matrix_sync(op + (size_t)(i * 16) * DV + j * 16,
                                        c2[i][j], DV, wmma::mem_row_major);
            }
        }
    }
}

// ---------------- launch ------------------------------------------------------
extern "C" void kernel_launch(void* const* d_in, const int* in_sizes, int n_in,
                              void* d_out, int out_size) {
    const float* Q     = (const float*)d_in[0];
    const float* K     = (const float*)d_in[1];
    const float* V     = (const float*)d_in[2];
    const float* omega = (const float*)d_in[3];
    float* out = (float*)d_out;

    cudaFuncSetAttribute(phi_wmma_kernel, cudaFuncAttributeMaxDynamicSharedMemorySize, PHI_SMEM);
    cudaFuncSetAttribute(fused_kernel,    cudaFuncAttributeMaxDynamicSharedMemorySize, SMEMF);

    omega_split_kernel<<<(D * M) / 256, 256>>>(omega);
    phi_wmma_kernel<<<2 * NTILES, 256, PHI_SMEM>>>(Q, K);
    fused_kernel<<<dim3(2, NB), 512, SMEMF>>>(V, out);
}

// round 14
// speedup vs baseline: 1.5806x; 1.0886x over previous
#include <cuda_runtime.h>
#include <cuda_fp16.h>
#include <mma.h>
#include <math.h>
#include <stdint.h>

using namespace nvcuda;

#define N_TOK 32768
#define NB 64
#define NP 512
#define D 128
#define M 256
#define DV 256
#define EPS_PHI 1e-4f
#define EPS_NORM 1e-8f
#define INV_SQRT_M 0.0625f
#define XSCALE 0.29730177875068026f   // 1/128^0.25
#define KSCALE 256.0f
#define QSCALE 256.0f
#define ESCALE 512.0f
#define C2F (EPS_PHI * INV_SQRT_M * KSCALE)
#define NORM_EPS (EPS_NORM * KSCALE * QSCALE)

#define NTILE 64
#define NTILES (N_TOK / NTILE)

// ---------------- scratch ------------------------------------------------------
__device__ float  g_bmax[NTILES];
__device__ float  g_esum[NTILES * M];
__device__ __align__(16) __half g_Qh[N_TOK * M];
__device__ __align__(16) __half g_Ke[N_TOK * M];
__device__ __align__(16) __half g_Whi[D * M];

__device__ __forceinline__ void cp16(uint32_t dst, const void* src) {
    asm volatile("cp.async.cg.shared.global [%0], [%1], 16;" :: "r"(dst), "l"(src));
}
__device__ __forceinline__ uint32_t h2bits(__half2 h) { return *(uint32_t*)&h; }

__global__ void omega_split_kernel(const float* __restrict__ omega) {
    int i = blockIdx.x * 256 + threadIdx.x;
    g_Whi[i] = __float2half_rn(omega[i]);
}

// ---------------- phi: U = X@omega, frag-direct epilogue (unchanged R13) -----
#define PHI_LDA 136
#define PHI_LDB 264
#define PHI_SMEM 88576

__global__ __launch_bounds__(256, 2) void phi_wmma_kernel(
    const float* __restrict__ Q, const float* __restrict__ K) {
    extern __shared__ char smraw[];
    __half* Ahi = (__half*)smraw;
    __half* Bhi = (__half*)(smraw + 17408);
    float*  hsm = (float*)(smraw + 84992);
    float*  mxs = (float*)(smraw + 85248);
    float*  mxs2 = (float*)(smraw + 85504);
    float*  esum2 = (float*)(smraw + 86528);
    const uint32_t sbase = (uint32_t)__cvta_generic_to_shared(smraw);

    const int tid  = threadIdx.x;
    const int warp = tid >> 5, lane = tid & 31;
    const int r4 = lane >> 2, q4 = lane & 3;
    const bool isq = blockIdx.x < NTILES;
    const int tile = isq ? blockIdx.x : blockIdx.x - NTILES;
    const int row0 = tile * NTILE;
    const float* X = isq ? Q : K;

#pragma unroll
    for (int u = 0; u < 16; u++) {
        int i = u * 256 + tid;
        int r = i >> 5, q = i & 31;
        cp16(sbase + 17408 + r * (PHI_LDB * 2) + q * 16, g_Whi + r * 256 + q * 8);
    }
    asm volatile("cp.async.commit_group;");

    {
        int r = tid >> 2, j = tid & 3;
        const float4* src = (const float4*)(X + (size_t)(row0 + r) * D + j * 32);
        __half* ah = Ahi + r * PHI_LDA + j * 32;
        float ss = 0.f;
#pragma unroll
        for (int q = 0; q < 8; q++) {
            float4 v = src[q];
            v.x *= XSCALE; v.y *= XSCALE; v.z *= XSCALE; v.w *= XSCALE;
            ss += v.x * v.x + v.y * v.y + v.z * v.z + v.w * v.w;
            uint2 w = make_uint2(h2bits(__floats2half2_rn(v.x, v.y)),
                                 h2bits(__floats2half2_rn(v.z, v.w)));
            *(uint2*)(ah + q * 4) = w;
        }
        ss += __shfl_xor_sync(0xffffffffu, ss, 1);
        ss += __shfl_xor_sync(0xffffffffu, ss, 2);
        if (j == 0) hsm[r] = 0.5f * ss;
    }
    asm volatile("cp.async.wait_group 0;");
    __syncthreads();

    const int wr = warp >> 2, wc = warp & 3;
    wmma::fragment<wmma::accumulator, 16, 16, 16, float> c[2][4];
#pragma unroll
    for (int i = 0; i < 2; i++)
#pragma unroll
        for (int j = 0; j < 4; j++) wmma::fill_fragment(c[i][j], 0.f);

#pragma unroll
    for (int ks = 0; ks < 8; ks++) {
        int kk = ks * 16;
        wmma::fragment<wmma::matrix_a, 16, 16, 16, __half, wmma::row_major> ah[2];
        wmma::fragment<wmma::matrix_b, 16, 16, 16, __half, wmma::row_major> bh[4];
#pragma unroll
        for (int i = 0; i < 2; i++)
            wmma::load_matrix_sync(ah[i], Ahi + (wr * 32 + i * 16) * PHI_LDA + kk, PHI_LDA);
#pragma unroll
        for (int j = 0; j < 4; j++)
            wmma::load_matrix_sync(bh[j], Bhi + kk * PHI_LDB + wc * 64 + j * 16, PHI_LDB);
#pragma unroll
        for (int i = 0; i < 2; i++)
#pragma unroll
            for (int j = 0; j < 4; j++)
                wmma::mma_sync(c[i][j], ah[i], bh[j], c[i][j]);
    }

    if (isq) {
#pragma unroll
        for (int i = 0; i < 2; i++) {
            float mA = -INFINITY, mB = -INFINITY;
#pragma unroll
            for (int j = 0; j < 4; j++) {
                mA = fmaxf(mA, fmaxf(fmaxf(c[i][j].x[0], c[i][j].x[1]),
                                     fmaxf(c[i][j].x[4], c[i][j].x[5])));
                mB = fmaxf(mB, fmaxf(fmaxf(c[i][j].x[2], c[i][j].x[3]),
                                     fmaxf(c[i][j].x[6], c[i][j].x[7])));
            }
            mA = fmaxf(mA, __shfl_xor_sync(0xffffffffu, mA, 1));
            mA = fmaxf(mA, __shfl_xor_sync(0xffffffffu, mA, 2));
            mB = fmaxf(mB, __shfl_xor_sync(0xffffffffu, mB, 1));
            mB = fmaxf(mB, __shfl_xor_sync(0xffffffffu, mB, 2));
            if (q4 == 0) {
                mxs2[(wr * 32 + i * 16 + r4) * 4 + wc]     = mA;
                mxs2[(wr * 32 + i * 16 + r4 + 8) * 4 + wc] = mB;
            }
        }
        __syncthreads();
        if (tid < 64)
            mxs[tid] = fmaxf(fmaxf(mxs2[tid * 4], mxs2[tid * 4 + 1]),
                             fmaxf(mxs2[tid * 4 + 2], mxs2[tid * 4 + 3]));
        __syncthreads();
#pragma unroll
        for (int i = 0; i < 2; i++) {
            int rowA = wr * 32 + i * 16 + r4, rowB = rowA + 8;
            float hmA = hsm[rowA] + mxs[rowA];
            float hmB = hsm[rowB] + mxs[rowB];
            __half2* dA = (__half2*)(g_Qh + (size_t)(row0 + rowA) * M);
            __half2* dB = (__half2*)(g_Qh + (size_t)(row0 + rowB) * M);
#pragma unroll
            for (int j = 0; j < 4; j++) {
                int cb2 = (wc * 64 + j * 16) / 2 + q4;
#pragma unroll
                for (int hf = 0; hf < 2; hf++) {
                    int kb = hf * 4;
                    float a0 = (__expf(c[i][j].x[kb + 0] - hmA) + EPS_PHI) * (INV_SQRT_M * QSCALE);
                    float a1 = (__expf(c[i][j].x[kb + 1] - hmA) + EPS_PHI) * (INV_SQRT_M * QSCALE);
                    float b0 = (__expf(c[i][j].x[kb + 2] - hmB) + EPS_PHI) * (INV_SQRT_M * QSCALE);
                    float b1 = (__expf(c[i][j].x[kb + 3] - hmB) + EPS_PHI) * (INV_SQRT_M * QSCALE);
                    dA[cb2 + hf * 4] = __floats2half2_rn(a0, a1);
                    dB[cb2 + hf * 4] = __floats2half2_rn(b0, b1);
                }
            }
        }
    } else {
        float bm = -INFINITY;
#pragma unroll
        for (int i = 0; i < 2; i++)
#pragma unroll
            for (int j = 0; j < 4; j++)
#pragma unroll
                for (int e = 0; e < 8; e++) bm = fmaxf(bm, c[i][j].x[e]);
#pragma unroll
        for (int o = 16; o > 0; o >>= 1) bm = fmaxf(bm, __shfl_xor_sync(0xffffffffu, bm, o));
        if (lane == 0) mxs[warp] = bm;
        __syncthreads();
        float bmax = mxs[0];
#pragma unroll
        for (int w = 1; w < 8; w++) bmax = fmaxf(bmax, mxs[w]);

        float es[16];
#pragma unroll
        for (int t = 0; t < 16; t++) es[t] = 0.f;
#pragma unroll
        for (int i = 0; i < 2; i++) {
            int rowA = wr * 32 + i * 16 + r4, rowB = rowA + 8;
            float hmA = hsm[rowA] + bmax;
            float hmB = hsm[rowB] + bmax;
            __half2* dA = (__half2*)(g_Ke + (size_t)(row0 + rowA) * M);
            __half2* dB = (__half2*)(g_Ke + (size_t)(row0 + rowB) * M);
#pragma unroll
            for (int j = 0; j < 4; j++) {
                int cb2 = (wc * 64 + j * 16) / 2 + q4;
#pragma unroll
                for (int hf = 0; hf < 2; hf++) {
                    int kb = hf * 4;
                    float a0 = __expf(c[i][j].x[kb + 0] - hmA) * ESCALE;
                    float a1 = __expf(c[i][j].x[kb + 1] - hmA) * ESCALE;
                    float b0 = __expf(c[i][j].x[kb + 2] - hmB) * ESCALE;
                    float b1 = __expf(c[i][j].x[kb + 3] - hmB) * ESCALE;
                    dA[cb2 + hf * 4] = __floats2half2_rn(a0, a1);
                    dB[cb2 + hf * 4] = __floats2half2_rn(b0, b1);
                    es[j * 4 + hf * 2 + 0] += a0 + b0;
                    es[j * 4 + hf * 2 + 1] += a1 + b1;
                }
            }
        }
#pragma unroll
        for (int t = 0; t < 16; t++) {
            es[t] += __shfl_xor_sync(0xffffffffu, es[t], 4);
            es[t] += __shfl_xor_sync(0xffffffffu, es[t], 8);
            es[t] += __shfl_xor_sync(0xffffffffu, es[t], 16);
        }
        if (lane < 4) {
#pragma unroll
            for (int j = 0; j < 4; j++)
#pragma unroll
                for (int hf = 0; hf < 2; hf++)
#pragma unroll
                    for (int p = 0; p < 2; p++) {
                        int col = wc * 64 + j * 16 + lane * 2 + p + 8 * hf;
                        esum2[wr * 256 + col] = es[j * 4 + hf * 2 + p];
                    }
        }
        __syncthreads();
        g_esum[tile * M + tid] = esum2[tid] + esum2[256 + tid];
        if (tid == 0) g_bmax[tile] = bmax;
    }
}

// ---------------- fused segment kernel ---------------------------------------
// KVs: [256][152] halves. Cols 0-127 KV, 128 Ksum_hi, 129 Ksum_lo, 130 ones,
// 131-143 zero. Norm computed as extra MMA columns by vc==3 warps.
#define LDA 264          // A stage stride (Ke / Qh tiles)
#define LDB 136          // phase-1 V tile stride
#define LDB2 152         // KVs stride
#define KVS_SZ  77824    // 256*152*2
#define ST_OFF  77824
#define ST_SZ   51200
#define AS2_OFF 77824
#define AS2_SZ  67584    // 128*264*2
#define KSM_OFF 212992
#define VSUM_OFF 214016
#define INV_OFF 214528
#define Q1_OFF  215040
#define SMEMF   215552

__global__ __launch_bounds__(512, 1) void fused_kernel(const float* __restrict__ V,
                                                       float* __restrict__ out) {
    extern __shared__ char smraw[];
    __half* KVs  = (__half*)smraw;
    float*  ksm  = (float*)(smraw + KSM_OFF);
    float*  vsum = (float*)(smraw + VSUM_OFF);
    float*  invbuf = (float*)(smraw + INV_OFF);
    float*  q1buf  = (float*)(smraw + Q1_OFF);
    const uint32_t sbase = (uint32_t)__cvta_generic_to_shared(smraw);

    const int tid = threadIdx.x, warp = tid >> 5, lane = tid & 31;
    const int r4 = lane >> 2, q4 = lane & 3;
    const int vh = blockIdx.x, b = blockIdx.y;

    float bm8[8];
#pragma unroll
    for (int cb = 0; cb < 8; cb++) bm8[cb] = g_bmax[b * 8 + cb];
    float sgm = bm8[0];
#pragma unroll
    for (int cb = 1; cb < 8; cb++) sgm = fmaxf(sgm, bm8[cb]);

    if (tid < M) {
        float s = 0.f;
#pragma unroll
        for (int cb = 0; cb < 8; cb++)
            s += __expf(bm8[cb] - sgm) * g_esum[(b * 8 + cb) * M + tid];
        float val = (s * (1.f / ESCALE) + NP * EPS_PHI) * (INV_SQRT_M * KSCALE);
        ksm[tid] = val;
        __half hhi = __float2half_rn(val);
        __half* kr = KVs + tid * LDB2;
        kr[128] = hhi;
        kr[129] = __float2half_rn(val - __half2float(hhi));
        kr[130] = __float2half_rn(1.0f);
#pragma unroll
        for (int z = 131; z < 144; z++) kr[z] = __float2half_rn(0.f);
    }
    if (tid < 128) vsum[tid] = 0.f;

    float corrf[8];
#pragma unroll
    for (int cb = 0; cb < 8; cb++)
        corrf[cb] = __expf(bm8[cb] - sgm) * (INV_SQRT_M * KSCALE / ESCALE);

    const __half* Ke = g_Ke + (size_t)b * NP * M;
    const float*  Vb = V    + (size_t)b * NP * DV + vh * 128;

    // ================= PHASE 1: KV-half into KVs =================
    const int wr1 = warp & 7, wv = warp >> 3;

    auto copyA = [&](int s, int ch) {
        uint32_t abase = sbase + ST_OFF + s * ST_SZ;
        const __half* src = Ke + (size_t)(ch * 64) * M;
#pragma unroll
        for (int u = 0; u < 4; u++) {
            int i = tid + u * 512, t = i >> 5, q = i & 31;
            cp16(abase + (t * LDA + q * 8) * 2, src + (size_t)t * M + q * 8);
        }
        asm volatile("cp.async.commit_group;");
    };

    float4 Breg[4], Breg2[4];
    auto loadB = [&](float4* rg, int ch) {
        const float* src = Vb + (size_t)(ch * 64) * DV;
#pragma unroll
        for (int u = 0; u < 4; u++) {
            int i = tid + u * 512, t = i >> 5, q = i & 31;
            rg[u] = ((const float4*)(src + (size_t)t * DV))[q];
        }
    };
    float4 vpart = make_float4(0.f, 0.f, 0.f, 0.f);
    auto storeB = [&](const float4* rg, int s, float cf) {
        __half* Bs = (__half*)(smraw + ST_OFF + s * ST_SZ + 33792);
#pragma unroll
        for (int u = 0; u < 4; u++) {
            int i = tid + u * 512, t = i >> 5, q = i & 31;
            float4 f = rg[u];
            vpart.x += f.x; vpart.y += f.y; vpart.z += f.z; vpart.w += f.w;
            uint2 w = make_uint2(h2bits(__floats2half2_rn(f.x * cf, f.y * cf)),
                                 h2bits(__floats2half2_rn(f.z * cf, f.w * cf)));
            *(uint2*)(Bs + t * LDB + q * 4) = w;
        }
    };

    wmma::fragment<wmma::accumulator, 16, 16, 16, float> c1[2][4];
#pragma unroll
    for (int i = 0; i < 2; i++)
#pragma unroll
        for (int j = 0; j < 4; j++) wmma::fill_fragment(c1[i][j], 0.f);

    copyA(0, 0);
    loadB(Breg, 0);

    for (int ch = 0; ch < 8; ch++) {
        int s = ch & 1;
        if (ch < 7) copyA(s ^ 1, ch + 1);
        if (ch < 7) asm volatile("cp.async.wait_group 1;");
        else        asm volatile("cp.async.wait_group 0;");
        storeB(Breg, s, corrf[ch]);
        __syncthreads();
        if (ch < 7) loadB(Breg2, ch + 1);

        const __half* As = (const __half*)(smraw + ST_OFF + s * ST_SZ);
        const __half* Bs = As + 33792 / 2;
#pragma unroll
        for (int kk = 0; kk < 64; kk += 16) {
            wmma::fragment<wmma::matrix_a, 16, 16, 16, __half, wmma::col_major> a[2];
#pragma unroll
            for (int i = 0; i < 2; i++)
                wmma::load_matrix_sync(a[i], As + kk * LDA + wr1 * 32 + i * 16, LDA);
#pragma unroll
            for (int j = 0; j < 4; j++) {
                wmma::fragment<wmma::matrix_b, 16, 16, 16, __half, wmma::row_major> bf;
                wmma::load_matrix_sync(bf, Bs + kk * LDB + wv * 64 + j * 16, LDB);
#pragma unroll
                for (int i = 0; i < 2; i++)
                    wmma::mma_sync(c1[i][j], a[i], bf, c1[i][j]);
            }
        }
        __syncthreads();
#pragma unroll
        for (int u = 0; u < 4; u++) Breg[u] = Breg2[u];
    }

    // phase-2 chunk-0 A prefetch (ST region now free)
    {
        uint32_t abase = sbase + AS2_OFF;
        const __half* src = g_Qh + (size_t)b * NP * M;
#pragma unroll
        for (int u = 0; u < 8; u++) {
            int i = tid + u * 512, t = i >> 5, q = i & 31;
            cp16(abase + (t * LDA + q * 8) * 2, src + (size_t)t * M + q * 8);
        }
        asm volatile("cp.async.commit_group;");
    }

    {
        int q = tid & 31;
        atomicAdd(&vsum[q * 4 + 0], vpart.x);
        atomicAdd(&vsum[q * 4 + 1], vpart.y);
        atomicAdd(&vsum[q * 4 + 2], vpart.z);
        atomicAdd(&vsum[q * 4 + 3], vpart.w);
    }
#pragma unroll
    for (int i = 0; i < 2; i++)
#pragma unroll
        for (int j = 0; j < 4; j++) {
            wmma::fragment<wmma::accumulator, 16, 16, 16, __half> hf;
#pragma unroll
            for (int e = 0; e < hf.num_elements; e++)
                hf.x[e] = __float2half_rn(c1[i][j].x[e]);
            wmma::store_matrix_sync(KVs + (wr1 * 32 + i * 16) * LDB2 + wv * 64 + j * 16,
                                    hf, LDB2, wmma::mem_row_major);
        }

    // ================= PHASE 2: 4 chunks of 128 tokens =================
    const int tr = warp >> 2, vc = warp & 3;
    const __half* Qh = g_Qh + (size_t)b * NP * M;

    for (int c = 0; c < 4; c++) {
        int s = c & 1;
        asm volatile("cp.async.wait_group 0;");
        __syncthreads();   // As2 stage s ready; KVs/vsum/invbuf safe to (re)use

        if (c < 3) {
            uint32_t abase = sbase + AS2_OFF + (s ^ 1) * AS2_SZ;
            const __half* src = Qh + (size_t)((c + 1) * 128) * M;
#pragma unroll
            for (int u = 0; u < 8; u++) {
                int i = tid + u * 512, t = i >> 5, q = i & 31;
                cp16(abase + (t * LDA + q * 8) * 2, src + (size_t)t * M + q * 8);
            }
            asm volatile("cp.async.commit_group;");
        }

        const __half* As2 = (const __half*)(smraw + AS2_OFF + s * AS2_SZ);

        wmma::fragment<wmma::accumulator, 16, 16, 16, float> c2[2][2];
        wmma::fragment<wmma::accumulator, 16, 16, 16, float> cn[2];
#pragma unroll
        for (int i = 0; i < 2; i++) {
#pragma unroll
            for (int j = 0; j < 2; j++) wmma::fill_fragment(c2[i][j], 0.f);
            wmma::fill_fragment(cn[i], 0.f);
        }

#pragma unroll
        for (int ks = 0; ks < 16; ks++) {
            int kk = ks * 16;
            wmma::fragment<wmma::matrix_a, 16, 16, 16, __half, wmma::row_major> a[2];
            wmma::fragment<wmma::matrix_b, 16, 16, 16, __half, wmma::row_major> bf[2];
#pragma unroll
            for (int i = 0; i < 2; i++)
                wmma::load_matrix_sync(a[i], As2 + (tr * 32 + i * 16) * LDA + kk, LDA);
#pragma unroll
            for (int j = 0; j < 2; j++)
                wmma::load_matrix_sync(bf[j], KVs + kk * LDB2 + vc * 32 + j * 16, LDB2);
#pragma unroll
            for (int i = 0; i < 2; i++)
#pragma unroll
                for (int j = 0; j < 2; j++)
                    wmma::mma_sync(c2[i][j], a[i], bf[j], c2[i][j]);
            if (vc == 3) {     // norm columns 128-143
                wmma::fragment<wmma::matrix_b, 16, 16, 16, __half, wmma::row_major> bn;
                wmma::load_matrix_sync(bn, KVs + kk * LDB2 + 128, LDB2);
#pragma unroll
                for (int i = 0; i < 2; i++)
                    wmma::mma_sync(cn[i], a[i], bn, cn[i]);
            }
        }

        if (vc == 3) {
            // col = 128 + q4*2 + (k&1) + 8*hf : q4==0 -> cols 128,129 (np),
            // q4==1 -> col 130 (qs)
#pragma unroll
            for (int i = 0; i < 2; i++) {
                int rowA = tr * 32 + i * 16 + r4, rowB = rowA + 8;
                if (q4 == 0) {
                    invbuf[rowA] = 1.0f / (cn[i].x[0] + cn[i].x[1] + NORM_EPS);
                    invbuf[rowB] = 1.0f / (cn[i].x[2] + cn[i].x[3] + NORM_EPS);
                } else if (q4 == 1) {
                    q1buf[rowA] = cn[i].x[0] * C2F;
                    q1buf[rowB] = cn[i].x[2] * C2F;
                }
            }
        }
        __syncthreads();

        // epilogue: fp32 rank-1 + inv scaling via frag layout, direct store
        float* op = out + ((size_t)(b * NP + c * 128 + tr * 32)) * DV + vh * 128 + vc * 32;
#pragma unroll
        for (int i = 0; i < 2; i++) {
            int rb = tr * 32 + i * 16;
            float invA = invbuf[rb + r4],     q1A = q1buf[rb + r4];
            float invB = invbuf[rb + r4 + 8], q1B = q1buf[rb + r4 + 8];
#pragma unroll
            for (int j = 0; j < 2; j++) {
                int cb = vc * 32 + j * 16 + q4 * 2;
                float vs0 = vsum[cb], vs1 = vsum[cb + 1];
                float vs8 = vsum[cb + 8], vs9 = vsum[cb + 9];
                c2[i][j].x[0] = (c2[i][j].x[0] + q1A * vs0) * invA;
                c2[i][j].x[1] = (c2[i][j].x[1] + q1A * vs1) * invA;
                c2[i][j].x[2] = (c2[i][j].x[2] + q1B * vs0) * invB;
                c2[i][j].x[3] = (c2[i][j].x[3] + q1B * vs1) * invB;
                c2[i][j].x[4] = (c2[i][j].x[4] + q1A * vs8) * invA;
                c2[i][j].x[5] = (c2[i][j].x[5] + q1A * vs9) * invA;
                c2[i][j].x[6] = (c2[i][j].x[6] + q1B * vs8) * invB;
                c2[i][j].x[7] = (c2[i][j].x[7] + q1B * vs9) * invB;
                wmma::store_matrix_sync(op + (size_t)(i * 16) * DV + j * 16,
                                        c2[i][j], DV, wmma::mem_row_major);
            }
        }
    }
}

// ---------------- launch ------------------------------------------------------
extern "C" void kernel_launch(void* const* d_in, const int* in_sizes, int n_in,
                              void* d_out, int out_size) {
    const float* Q     = (const float*)d_in[0];
    const float* K     = (const float*)d_in[1];
    const float* V     = (const float*)d_in[2];
    const float* omega = (const float*)d_in[3];
    float* out = (float*)d_out;

    cudaFuncSetAttribute(phi_wmma_kernel, cudaFuncAttributeMaxDynamicSharedMemorySize, PHI_SMEM);
    cudaFuncSetAttribute(fused_kernel,    cudaFuncAttributeMaxDynamicSharedMemorySize, SMEMF);

    omega_split_kernel<<<(D * M) / 256, 256>>>(omega);
    phi_wmma_kernel<<<2 * NTILES, 256, PHI_SMEM>>>(Q, K);
    fused_kernel<<<dim3(2, NB), 512, SMEMF>>>(V, out);
}